// round 14
// baseline (speedup 1.0000x reference)
#include <cuda_runtime.h>

#define B 128
#define L 200
#define D 50
#define H 5
#define E 10
#define NB 2
#define DH 10

typedef unsigned long long ull;

#define FMA2(d,a,b,c) asm("fma.rn.f32x2 %0, %1, %2, %3;" : "=l"(d) : "l"(a), "l"(b), "l"(c))

__device__ __forceinline__ float hadd2(ull v) {
    float lo, hi; asm("mov.b64 {%0,%1}, %2;" : "=f"(lo), "=f"(hi) : "l"(v)); return lo + hi;
}
__device__ __forceinline__ ull pack2(float a, float b) {
    ull r; asm("mov.b64 %0, {%1,%2};" : "=l"(r) : "f"(a), "f"(b)); return r;
}
__device__ __forceinline__ void unpk2(ull v, float& lo, float& hi) {
    asm("mov.b64 {%0,%1}, %2;" : "=f"(lo), "=f"(hi) : "l"(v));
}

// ---------------- scratch (device globals; allocation-free) ----------------
__device__ __align__(16) float g_seqs[B*L*D];
__device__ __align__(16) float g_tmp [B*L*D];
__device__ __align__(16) float g_Qn  [B*L*D];
__device__ __align__(16) float g_gate[B*E];
// q/k/v component-major: ull index ((be*H + h)*5 + d2)*200 + l   (d2 = dh pair)
__device__ __align__(16) float g_q   [B*E*H*L*DH];
__device__ __align__(16) float g_k   [B*E*H*L*DH];
__device__ __align__(16) float g_v   [B*E*H*L*DH];
__device__ __align__(16) float g_ctx [B*E*L*D];      // [be, l, d]  (gate pre-folded)

// ---------------- gate MLP ----------------
__global__ void k_gate(const float* __restrict__ item_emb,
                       const float* __restrict__ rW1, const float* __restrict__ rb1,
                       const float* __restrict__ rW2, const float* __restrict__ rb2,
                       const int* __restrict__ log_seqs) {
    __shared__ float mean[D];
    __shared__ float h[100];
    __shared__ float logit[E];
    int b = blockIdx.x, t = threadIdx.x;
    if (t < D) {
        float acc = 0.f;
        for (int l = 0; l < L; ++l) {
            int it = log_seqs[b*L + l];
            acc += item_emb[it*D + t];
        }
        mean[t] = acc * (7.0710678118654755f / 200.0f);
    }
    __syncthreads();
    if (t < 100) {
        float acc = rb1[t];
        #pragma unroll
        for (int d = 0; d < D; ++d) acc = fmaf(mean[d], rW1[t*D + d], acc);
        h[t] = fmaxf(acc, 0.f);
    }
    __syncthreads();
    if (t < E) {
        float acc = rb2[t];
        #pragma unroll
        for (int j = 0; j < 100; ++j) acc = fmaf(h[j], rW2[t*100 + j], acc);
        logit[t] = acc;
    }
    __syncthreads();
    if (t == 0) {
        float m = -1e30f;
        #pragma unroll
        for (int e = 0; e < E; ++e) m = fmaxf(m, logit[e]);
        float s = 0.f; float ex[E];
        #pragma unroll
        for (int e = 0; e < E; ++e) { ex[e] = expf(logit[e] - m); s += ex[e]; }
        float inv = 1.0f / s;
        #pragma unroll
        for (int e = 0; e < E; ++e) g_gate[b*E + e] = ex[e] * inv;
    }
}

// ---------------- embedding + positional ----------------
__global__ void k_embed(const float* __restrict__ item_emb,
                        const float* __restrict__ pos_emb,
                        const int* __restrict__ log_seqs) {
    int idx = blockIdx.x*blockDim.x + threadIdx.x;
    if (idx >= B*L*D) return;
    int d = idx % D; int bl = idx / D; int l = bl % L; int b = bl / L;
    int it = log_seqs[b*L + l];
    int pos = (it != 0) ? (l + 1) : 0;
    g_seqs[idx] = item_emb[it*D + d] * 7.0710678118654755f + pos_emb[pos*D + d];
}

// ---------------- layernorm: warp per row ----------------
__global__ void k_ln(int mode, const float* __restrict__ g, const float* __restrict__ bb) {
    int warp = (blockIdx.x*blockDim.x + threadIdx.x) >> 5;
    int lane = threadIdx.x & 31;
    if (warp >= B*L) return;
    const float* in  = (mode == 0) ? g_seqs : g_tmp;
    float*       out = (mode == 0) ? g_Qn   : g_seqs;
    const float* x = in + warp*D;
    float x0 = (lane < D)      ? x[lane]      : 0.f;
    float x1 = (lane + 32 < D) ? x[lane + 32] : 0.f;
    float s = x0 + x1;
    #pragma unroll
    for (int o = 16; o; o >>= 1) s += __shfl_xor_sync(~0u, s, o);
    float m = s * (1.0f / D);
    float d0 = (lane < D)      ? x0 - m : 0.f;
    float d1 = (lane + 32 < D) ? x1 - m : 0.f;
    float v = d0*d0 + d1*d1;
    #pragma unroll
    for (int o = 16; o; o >>= 1) v += __shfl_xor_sync(~0u, v, o);
    float inv = rsqrtf(v * (1.0f / D) + 1e-8f);
    float* y = out + warp*D;
    if (lane < D)      y[lane]      = fmaf(d0*inv, g[lane],      bb[lane]);
    if (lane + 32 < D) y[lane + 32] = fmaf(d1*inv, g[lane + 32], bb[lane + 32]);
}

// ---------------- QKV v6: CTA per (b, rowhalf, expertpair); warp = head; 4 rows/lane ----------------
// smem (ull units): XQ @0 [2525], XS @2525 [2525], W @5050 [3750], bias floats @8800
#define QKV_SMEM_BYTES (8800*8 + 152*4)

__global__ void __launch_bounds__(160) k_qkv(const float* __restrict__ in_w,
                                             const float* __restrict__ in_b, int blk) {
    extern __shared__ __align__(16) ull sm[];
    ull* XQ = sm;                  // [i*101 + row] (row local 0..99)
    ull* XS = sm + 2525;
    ull* W  = sm + 5050;           // [i*150 + f]
    float* sbias = (float*)(sm + 8800);
    int b = blockIdx.x;
    int l0 = blockIdx.y * 100;
    int e0 = blockIdx.z * 2;
    int tid = threadIdx.x;
    int wid = tid >> 5, lane = tid & 31;
    int f0base = wid * 10;                 // warp = feature group (head) -> uniform W reads
    int r3 = 96 + (lane & 3);              // clamped 4th row (lanes>=4 duplicate, discarded)

    // stage X transposed (once)
    {
        const ull* gq = (const ull*)g_Qn   + ((size_t)b*L + l0)*25;
        const ull* gs = (const ull*)g_seqs + ((size_t)b*L + l0)*25;
        for (int o = tid; o < 2500; o += 160) {
            int row = o / 25, i = o - row*25;
            XQ[i*101 + row] = gq[o];
            XS[i*101 + row] = gs[o];
        }
    }

    #pragma unroll 1
    for (int e = e0; e < e0 + 2; ++e) {
        __syncthreads();   // W readers of previous expert done (also orders staging at e=e0)
        {
            const ull* Wg = (const ull*)(in_w + (size_t)(blk*E + e)*7500);
            for (int o = tid; o < 3750; o += 160) {
                int f = o / 25, i = o - f*25;
                W[i*150 + f] = Wg[o];
            }
            for (int o = tid; o < 150; o += 160) sbias[o] = in_b[(blk*E + e)*150 + o];
        }
        __syncthreads();

        #pragma unroll 1
        for (int pass = 0; pass < 3; ++pass) {
            const ull* X = (pass == 0) ? XQ : XS;
            int f0 = pass*50 + f0base;
            ull acc[4][10];
            #pragma unroll
            for (int r = 0; r < 4; ++r)
                #pragma unroll
                for (int j = 0; j < 10; ++j) acc[r][j] = 0ull;
            #pragma unroll 5
            for (int i = 0; i < 25; ++i) {
                const ull* xc = X + i*101;
                ull x0 = xc[lane];
                ull x1 = xc[lane + 32];
                ull x2 = xc[lane + 64];
                ull x3 = xc[r3];
                const ull* wp = W + i*150 + f0;   // uniform across warp -> broadcast
                #pragma unroll
                for (int j2 = 0; j2 < 5; ++j2) {
                    ulonglong2 w2 = *(const ulonglong2*)(wp + 2*j2);
                    FMA2(acc[0][2*j2],   w2.x, x0, acc[0][2*j2]);
                    FMA2(acc[0][2*j2+1], w2.y, x0, acc[0][2*j2+1]);
                    FMA2(acc[1][2*j2],   w2.x, x1, acc[1][2*j2]);
                    FMA2(acc[1][2*j2+1], w2.y, x1, acc[1][2*j2+1]);
                    FMA2(acc[2][2*j2],   w2.x, x2, acc[2][2*j2]);
                    FMA2(acc[2][2*j2+1], w2.y, x2, acc[2][2*j2+1]);
                    FMA2(acc[3][2*j2],   w2.x, x3, acc[3][2*j2]);
                    FMA2(acc[3][2*j2+1], w2.y, x3, acc[3][2*j2+1]);
                }
            }
            {
                float* arr = (pass == 0) ? g_q : (pass == 1) ? g_k : g_v;
                // feature f = pass*50 + wid*10 + 2*j2(+1) -> head wid, dh-pair j2
                ull* dst = (ull*)arr + ((size_t)(b*E + e)*H + wid)*1000;
                #pragma unroll
                for (int r = 0; r < 3; ++r) {
                    int row = l0 + lane + 32*r;
                    #pragma unroll
                    for (int j2 = 0; j2 < 5; ++j2) {
                        float v0 = hadd2(acc[r][2*j2])   + sbias[f0 + 2*j2];
                        float v1 = hadd2(acc[r][2*j2+1]) + sbias[f0 + 2*j2 + 1];
                        dst[j2*200 + row] = pack2(v0, v1);   // dense across lanes
                    }
                }
                if (lane < 4) {
                    int row = l0 + 96 + lane;
                    #pragma unroll
                    for (int j2 = 0; j2 < 5; ++j2) {
                        float v0 = hadd2(acc[3][2*j2])   + sbias[f0 + 2*j2];
                        float v1 = hadd2(acc[3][2*j2+1]) + sbias[f0 + 2*j2 + 1];
                        dst[j2*200 + row] = pack2(v0, v1);
                    }
                }
            }
        }
    }
}

// ---------------- attention: 2 query rows per lane, vectorized k/v (rows padded to 6 ull) ----------------
__global__ void __launch_bounds__(128) k_attn() {
    int id = blockIdx.x;            // (b*E+e)*H + h
    int h = id % H; int be = id / H;
    __shared__ __align__(16) ull ks[1200];   // row-major [j*6 + d2], pad 1 ull/row
    __shared__ __align__(16) ull vs[1200];
    {
        const ull* kb = (const ull*)g_k + (size_t)(be*H + h)*1000;   // [d2*200 + l]
        const ull* vb = (const ull*)g_v + (size_t)(be*H + h)*1000;
        for (int o = threadIdx.x; o < 1000; o += 128) {
            int d2 = o / 200, l = o - d2*200;
            ks[l*6 + d2] = kb[o];
            vs[l*6 + d2] = vb[o];
        }
    }
    __syncthreads();
    int w = threadIdx.x >> 5, lane = threadIdx.x & 31;
    int r0 = w*64 + lane*2, r1 = r0 + 1;
    bool valid = r0 < L;
    int rb = valid ? r0 : 0;
    const float scale = 0.31622776601683794f;   // 1/sqrt(10)
    ull q0[5], q1[5];
    {
        const ull* qb = (const ull*)g_q + (size_t)(be*H + h)*1000;
        #pragma unroll
        for (int d = 0; d < 5; ++d) {
            ulonglong2 qq = *(const ulonglong2*)(qb + d*200 + rb);   // rows r0, r1
            q0[d] = qq.x; q1[d] = qq.y;
        }
    }
    int jmax = w*64 + 64; if (jmax > L) jmax = L;
    float ps0 = 0.f, ps1 = 0.f;
    ull a0[5] = {0,0,0,0,0}, a1[5] = {0,0,0,0,0};
    #pragma unroll 2
    for (int j = 0; j < jmax; ++j) {
        const ull* kj = ks + j*6;
        const ull* vj = vs + j*6;
        ulonglong2 kA = *(const ulonglong2*)(kj);
        ulonglong2 kB = *(const ulonglong2*)(kj + 2);
        ull        kC = kj[4];
        ull s0 = 0ull, s1 = 0ull;
        FMA2(s0, q0[0], kA.x, s0);  FMA2(s1, q1[0], kA.x, s1);
        FMA2(s0, q0[1], kA.y, s0);  FMA2(s1, q1[1], kA.y, s1);
        FMA2(s0, q0[2], kB.x, s0);  FMA2(s1, q1[2], kB.x, s1);
        FMA2(s0, q0[3], kB.y, s0);  FMA2(s1, q1[3], kB.y, s1);
        FMA2(s0, q0[4], kC,   s0);  FMA2(s1, q1[4], kC,   s1);
        float sc0 = hadd2(s0) * scale;
        float sc1 = hadd2(s1) * scale;
        float p0 = (j <= r0) ? __expf(sc0) : 0.f;
        float p1 = (j <= r1) ? __expf(sc1) : 0.f;
        ps0 += p0; ps1 += p1;
        ull pp0 = pack2(p0, p0), pp1 = pack2(p1, p1);
        ulonglong2 vA = *(const ulonglong2*)(vj);
        ulonglong2 vB = *(const ulonglong2*)(vj + 2);
        ull        vC = vj[4];
        FMA2(a0[0], pp0, vA.x, a0[0]);  FMA2(a1[0], pp1, vA.x, a1[0]);
        FMA2(a0[1], pp0, vA.y, a0[1]);  FMA2(a1[1], pp1, vA.y, a1[1]);
        FMA2(a0[2], pp0, vB.x, a0[2]);  FMA2(a1[2], pp1, vB.x, a1[2]);
        FMA2(a0[3], pp0, vB.y, a0[3]);  FMA2(a1[3], pp1, vB.y, a1[3]);
        FMA2(a0[4], pp0, vC,   a0[4]);  FMA2(a1[4], pp1, vC,   a1[4]);
    }
    if (valid) {
        int b = be / E, e = be - b*E;
        float gt = g_gate[b*E + e];
        float i0 = gt / ps0, i1 = gt / ps1;
        ull* c0 = (ull*)g_ctx + ((size_t)be*L + r0)*25 + h*5;
        ull* c1 = (ull*)g_ctx + ((size_t)be*L + r1)*25 + h*5;
        #pragma unroll
        for (int d = 0; d < 5; ++d) {
            float lo, hi;
            unpk2(a0[d], lo, hi); c0[d] = pack2(lo*i0, hi*i0);
            unpk2(a1[d], lo, hi); c1[d] = pack2(lo*i1, hi*i1);
        }
    }
}

// ---------------- out-proj + bias-mix + residual: CTA per (b, half); 2x10 reg tile ----------------
__global__ void __launch_bounds__(256) k_combine(const float* __restrict__ out_w,
                                                 const float* __restrict__ out_b, int blk) {
    __shared__ __align__(16) ull CT[2525];   // transposed ctx [i*101 + row]; reused as SOUT
    __shared__ __align__(16) ull WT[1250];   // [i*50 + f] W[f][2i..2i+1]
    int b = blockIdx.x;
    int l0 = blockIdx.y * 100;
    int tid = threadIdx.x;
    bool act = tid < 250;
    int fg = tid / 50;           // 0..4
    int rg = tid - fg*50;        // rows rg, rg+50 (local)
    ull acc[2][10];
    #pragma unroll
    for (int r = 0; r < 2; ++r)
        #pragma unroll
        for (int j = 0; j < 10; ++j) acc[r][j] = 0ull;
    float bm[10];
    #pragma unroll
    for (int j = 0; j < 10; ++j) bm[j] = 0.f;

    for (int e = 0; e < E; ++e) {
        __syncthreads();
        {
            const ull* Wg = (const ull*)(out_w + (size_t)(blk*E + e)*2500);
            for (int o = tid; o < 1250; o += 256) {
                int f = o / 25, i = o - f*25;
                WT[i*50 + f] = Wg[o];
            }
            const ull* cg = (const ull*)g_ctx + ((size_t)(b*E + e)*L + l0)*25;
            for (int o = tid; o < 2500; o += 256) {
                int row = o / 25, i = o - row*25;
                CT[i*101 + row] = cg[o];
            }
        }
        float ge = g_gate[b*E + e];
        if (act) {
            #pragma unroll
            for (int j = 0; j < 10; ++j)
                bm[j] = fmaf(ge, out_b[(blk*E + e)*D + fg*10 + j], bm[j]);
        }
        __syncthreads();
        if (act) {
            #pragma unroll 5
            for (int i = 0; i < 25; ++i) {
                ull x0 = CT[i*101 + rg];
                ull x1 = CT[i*101 + rg + 50];
                const ull* wp = WT + i*50 + fg*10;
                #pragma unroll
                for (int j2 = 0; j2 < 5; ++j2) {
                    ulonglong2 w2 = *(const ulonglong2*)(wp + 2*j2);
                    FMA2(acc[0][2*j2],   w2.x, x0, acc[0][2*j2]);
                    FMA2(acc[0][2*j2+1], w2.y, x0, acc[0][2*j2+1]);
                    FMA2(acc[1][2*j2],   w2.x, x1, acc[1][2*j2]);
                    FMA2(acc[1][2*j2+1], w2.y, x1, acc[1][2*j2+1]);
                }
            }
        }
    }
    __syncthreads();
    if (act) {
        #pragma unroll
        for (int r = 0; r < 2; ++r) {
            int row = rg + 50*r;
            #pragma unroll
            for (int j2 = 0; j2 < 5; ++j2) {
                float v0 = hadd2(acc[r][2*j2])   + bm[2*j2];
                float v1 = hadd2(acc[r][2*j2+1]) + bm[2*j2+1];
                CT[row*25 + fg*5 + j2] = pack2(v0, v1);
            }
        }
    }
    __syncthreads();
    {
        const ull* qn = (const ull*)g_Qn + ((size_t)b*L + l0)*25;
        ull* dst = (ull*)g_tmp + ((size_t)b*L + l0)*25;
        for (int o = tid; o < 2500; o += 256) {
            float a, bb2, c, d;
            unpk2(CT[o], a, bb2);
            unpk2(qn[o], c, d);
            dst[o] = pack2(a + c, bb2 + d);
        }
    }
}

// ---------------- FFN v2: CTA per (b, half); 2x10 reg tile; transposed smem ----------------
#define FFN_SMEM_BYTES (7550*8 + 104*4)

__global__ void __launch_bounds__(256) k_ffn(const float* __restrict__ f1_w, const float* __restrict__ f1_b,
                                             const float* __restrict__ f2_w, const float* __restrict__ f2_b,
                                             int blk) {
    extern __shared__ __align__(16) ull sf[];
    ull* XT  = sf;            // [i*101 + row]; later reused as SOUT (row*25 + i)
    ull* HT  = sf + 2525;
    ull* W1T = sf + 5050;
    ull* W2T = sf + 6300;
    float* b1s = (float*)(sf + 7550);
    float* b2s = b1s + 50;
    int b = blockIdx.x;
    int l0 = blockIdx.y * 100;
    int tid = threadIdx.x;
    bool act = tid < 250;
    int fg = act ? tid / 50 : 0;
    int rg = act ? tid - fg*50 : 0;

    {
        const ull* gs = (const ull*)g_seqs + ((size_t)b*L + l0)*25;
        for (int o = tid; o < 2500; o += 256) {
            int row = o / 25, i = o - row*25;
            XT[i*101 + row] = gs[o];
        }
        const ull* W1g = (const ull*)(f1_w + (size_t)blk*2500);
        const ull* W2g = (const ull*)(f2_w + (size_t)blk*2500);
        for (int o = tid; o < 1250; o += 256) {
            int f = o / 25, i = o - f*25;
            W1T[i*50 + f] = W1g[o];
            W2T[i*50 + f] = W2g[o];
        }
        if (tid < 50) { b1s[tid] = f1_b[blk*D + tid]; b2s[tid] = f2_b[blk*D + tid]; }
    }
    __syncthreads();

    int f0 = fg*10;
    {
        ull acc[2][10];
        #pragma unroll
        for (int r = 0; r < 2; ++r)
            #pragma unroll
            for (int j = 0; j < 10; ++j) acc[r][j] = 0ull;
        #pragma unroll 5
        for (int i = 0; i < 25; ++i) {
            ull x0 = XT[i*101 + rg];
            ull x1 = XT[i*101 + rg + 50];
            const ull* wp = W1T + i*50 + f0;
            #pragma unroll
            for (int j2 = 0; j2 < 5; ++j2) {
                ulonglong2 w2 = *(const ulonglong2*)(wp + 2*j2);
                FMA2(acc[0][2*j2],   w2.x, x0, acc[0][2*j2]);
                FMA2(acc[0][2*j2+1], w2.y, x0, acc[0][2*j2+1]);
                FMA2(acc[1][2*j2],   w2.x, x1, acc[1][2*j2]);
                FMA2(acc[1][2*j2+1], w2.y, x1, acc[1][2*j2+1]);
            }
        }
        if (act) {
            #pragma unroll
            for (int r = 0; r < 2; ++r) {
                #pragma unroll
                for (int j2 = 0; j2 < 5; ++j2) {
                    float h0 = fmaxf(hadd2(acc[r][2*j2])   + b1s[f0 + 2*j2],     0.f);
                    float h1 = fmaxf(hadd2(acc[r][2*j2+1]) + b1s[f0 + 2*j2 + 1], 0.f);
                    HT[(fg*5 + j2)*101 + rg + 50*r] = pack2(h0, h1);
                }
            }
        }
    }
    __syncthreads();
    {
        ull acc[2][10];
        #pragma unroll
        for (int r = 0; r < 2; ++r)
            #pragma unroll
            for (int j = 0; j < 10; ++j) acc[r][j] = 0ull;
        #pragma unroll 5
        for (int i = 0; i < 25; ++i) {
            ull h0 = HT[i*101 + rg];
            ull h1 = HT[i*101 + rg + 50];
            const ull* wp = W2T + i*50 + f0;
            #pragma unroll
            for (int j2 = 0; j2 < 5; ++j2) {
                ulonglong2 w2 = *(const ulonglong2*)(wp + 2*j2);
                FMA2(acc[0][2*j2],   w2.x, h0, acc[0][2*j2]);
                FMA2(acc[0][2*j2+1], w2.y, h0, acc[0][2*j2+1]);
                FMA2(acc[1][2*j2],   w2.x, h1, acc[1][2*j2]);
                FMA2(acc[1][2*j2+1], w2.y, h1, acc[1][2*j2+1]);
            }
        }
        if (act) {
            #pragma unroll
            for (int r = 0; r < 2; ++r) {
                int row = rg + 50*r;
                #pragma unroll
                for (int j2 = 0; j2 < 5; ++j2) {
                    float o0 = hadd2(acc[r][2*j2])   + b2s[f0 + 2*j2];
                    float o1 = hadd2(acc[r][2*j2+1]) + b2s[f0 + 2*j2 + 1];
                    XT[row*25 + fg*5 + j2] = pack2(o0, o1);   // SOUT
                }
            }
        }
    }
    __syncthreads();
    {
        ull* gs = (ull*)g_seqs + ((size_t)b*L + l0)*25;
        for (int o = tid; o < 2500; o += 256) {
            float a, bb2, c, d;
            unpk2(XT[o], a, bb2);
            unpk2(gs[o], c, d);
            gs[o] = pack2(a + c, bb2 + d);
        }
    }
}

// ---------------- final LN + pos/neg logits ----------------
__global__ void k_final(const float* __restrict__ lnf_g, const float* __restrict__ lnf_b,
                        const float* __restrict__ item_emb,
                        const int* __restrict__ pos_seqs, const int* __restrict__ neg_seqs,
                        float* __restrict__ out) {
    int warp = (blockIdx.x*blockDim.x + threadIdx.x) >> 5;
    int lane = threadIdx.x & 31;
    if (warp >= B*L) return;
    const float* x = g_seqs + warp*D;
    float x0 = (lane < D)      ? x[lane]      : 0.f;
    float x1 = (lane + 32 < D) ? x[lane + 32] : 0.f;
    float s = x0 + x1;
    #pragma unroll
    for (int o = 16; o; o >>= 1) s += __shfl_xor_sync(~0u, s, o);
    float m = s * (1.0f / D);
    float d0 = (lane < D)      ? x0 - m : 0.f;
    float d1 = (lane + 32 < D) ? x1 - m : 0.f;
    float v = d0*d0 + d1*d1;
    #pragma unroll
    for (int o = 16; o; o >>= 1) v += __shfl_xor_sync(~0u, v, o);
    float inv = rsqrtf(v * (1.0f / D) + 1e-8f);
    float f0 = (lane < D)      ? fmaf(d0*inv, lnf_g[lane],      lnf_b[lane])      : 0.f;
    float f1 = (lane + 32 < D) ? fmaf(d1*inv, lnf_g[lane + 32], lnf_b[lane + 32]) : 0.f;
    int ip = pos_seqs[warp], in_ = neg_seqs[warp];
    const float* pe = item_emb + (size_t)ip*D;
    const float* ne = item_emb + (size_t)in_*D;
    float dp = 0.f, dn = 0.f;
    if (lane < D)      { dp = f0*pe[lane];                 dn = f0*ne[lane]; }
    if (lane + 32 < D) { dp = fmaf(f1, pe[lane + 32], dp); dn = fmaf(f1, ne[lane + 32], dn); }
    #pragma unroll
    for (int o = 16; o; o >>= 1) {
        dp += __shfl_xor_sync(~0u, dp, o);
        dn += __shfl_xor_sync(~0u, dn, o);
    }
    if (lane == 0) { out[warp] = dp; out[B*L + warp] = dn; }
}

// ---------------- launch ----------------
extern "C" void kernel_launch(void* const* d_in, const int* in_sizes, int n_in,
                              void* d_out, int out_size) {
    const float* item_emb = (const float*)d_in[0];
    const float* pos_emb  = (const float*)d_in[1];
    const float* rW1      = (const float*)d_in[2];
    const float* rb1      = (const float*)d_in[3];
    const float* rW2      = (const float*)d_in[4];
    const float* rb2      = (const float*)d_in[5];
    const float* ln1_g    = (const float*)d_in[6];
    const float* ln1_b    = (const float*)d_in[7];
    const float* in_w     = (const float*)d_in[8];
    const float* in_b     = (const float*)d_in[9];
    const float* out_w    = (const float*)d_in[10];
    const float* out_b    = (const float*)d_in[11];
    const float* ln2_g    = (const float*)d_in[12];
    const float* ln2_b    = (const float*)d_in[13];
    const float* f1_w     = (const float*)d_in[14];
    const float* f1_b     = (const float*)d_in[15];
    const float* f2_w     = (const float*)d_in[16];
    const float* f2_b     = (const float*)d_in[17];
    const float* lnf_g    = (const float*)d_in[18];
    const float* lnf_b    = (const float*)d_in[19];
    const int*   log_seqs = (const int*)d_in[21];
    const int*   pos_seqs = (const int*)d_in[22];
    const int*   neg_seqs = (const int*)d_in[23];
    float* out = (float*)d_out;

    cudaFuncSetAttribute(k_qkv, cudaFuncAttributeMaxDynamicSharedMemorySize, QKV_SMEM_BYTES);
    cudaFuncSetAttribute(k_ffn, cudaFuncAttributeMaxDynamicSharedMemorySize, FFN_SMEM_BYTES);

    k_gate<<<B, 128>>>(item_emb, rW1, rb1, rW2, rb2, log_seqs);
    k_embed<<<(B*L*D + 255)/256, 256>>>(item_emb, pos_emb, log_seqs);

    for (int blk = 0; blk < NB; ++blk) {
        k_ln<<<(B*L + 7)/8, 256>>>(0, ln1_g + blk*D, ln1_b + blk*D);
        k_qkv<<<dim3(B, 2, 5), 160, QKV_SMEM_BYTES>>>(in_w, in_b, blk);
        k_attn<<<B*E*H, 128>>>();
        k_combine<<<dim3(B, 2), 256>>>(out_w, out_b, blk);
        k_ln<<<(B*L + 7)/8, 256>>>(1, ln2_g + blk*D, ln2_b + blk*D);
        k_ffn<<<dim3(B, 2), 256, FFN_SMEM_BYTES>>>(f1_w, f1_b, f2_w, f2_b, blk);
    }

    k_final<<<(B*L + 7)/8, 256>>>(lnf_g, lnf_b, item_emb, pos_seqs, neg_seqs, out);
}

// round 15
// speedup vs baseline: 1.1524x; 1.1524x over previous
#include <cuda_runtime.h>

#define B 128
#define L 200
#define D 50
#define H 5
#define E 10
#define NB 2
#define DH 10

typedef unsigned long long ull;

#define FMA2(d,a,b,c) asm("fma.rn.f32x2 %0, %1, %2, %3;" : "=l"(d) : "l"(a), "l"(b), "l"(c))

__device__ __forceinline__ float hadd2(ull v) {
    float lo, hi; asm("mov.b64 {%0,%1}, %2;" : "=f"(lo), "=f"(hi) : "l"(v)); return lo + hi;
}
__device__ __forceinline__ ull pack2(float a, float b) {
    ull r; asm("mov.b64 %0, {%1,%2};" : "=l"(r) : "f"(a), "f"(b)); return r;
}
__device__ __forceinline__ void unpk2(ull v, float& lo, float& hi) {
    asm("mov.b64 {%0,%1}, %2;" : "=f"(lo), "=f"(hi) : "l"(v));
}

// ---------------- scratch (device globals; allocation-free) ----------------
__device__ __align__(16) float g_seqs[B*L*D];
__device__ __align__(16) float g_Qn  [B*L*D];
__device__ __align__(16) float g_gate[B*E];
// q/k/v component-major: ull index ((be*H + h)*5 + d2)*200 + l   (d2 = dh pair)
__device__ __align__(16) float g_q   [B*E*H*L*DH];
__device__ __align__(16) float g_k   [B*E*H*L*DH];
__device__ __align__(16) float g_v   [B*E*H*L*DH];
__device__ __align__(16) float g_ctx [B*E*L*D];      // [be, l, d]  (gate pre-folded)

// ---------------- gate MLP ----------------
__global__ void k_gate(const float* __restrict__ item_emb,
                       const float* __restrict__ rW1, const float* __restrict__ rb1,
                       const float* __restrict__ rW2, const float* __restrict__ rb2,
                       const int* __restrict__ log_seqs) {
    __shared__ float mean[D];
    __shared__ float h[100];
    __shared__ float logit[E];
    int b = blockIdx.x, t = threadIdx.x;
    if (t < D) {
        float acc = 0.f;
        for (int l = 0; l < L; ++l) {
            int it = log_seqs[b*L + l];
            acc += item_emb[it*D + t];
        }
        mean[t] = acc * (7.0710678118654755f / 200.0f);
    }
    __syncthreads();
    if (t < 100) {
        float acc = rb1[t];
        #pragma unroll
        for (int d = 0; d < D; ++d) acc = fmaf(mean[d], rW1[t*D + d], acc);
        h[t] = fmaxf(acc, 0.f);
    }
    __syncthreads();
    if (t < E) {
        float acc = rb2[t];
        #pragma unroll
        for (int j = 0; j < 100; ++j) acc = fmaf(h[j], rW2[t*100 + j], acc);
        logit[t] = acc;
    }
    __syncthreads();
    if (t == 0) {
        float m = -1e30f;
        #pragma unroll
        for (int e = 0; e < E; ++e) m = fmaxf(m, logit[e]);
        float s = 0.f; float ex[E];
        #pragma unroll
        for (int e = 0; e < E; ++e) { ex[e] = expf(logit[e] - m); s += ex[e]; }
        float inv = 1.0f / s;
        #pragma unroll
        for (int e = 0; e < E; ++e) g_gate[b*E + e] = ex[e] * inv;
    }
}

// ---------------- embedding + positional + LN1(blk0): warp per row ----------------
__global__ void k_embed_ln(const float* __restrict__ item_emb,
                           const float* __restrict__ pos_emb,
                           const int* __restrict__ log_seqs,
                           const float* __restrict__ g, const float* __restrict__ bb) {
    int warp = (blockIdx.x*blockDim.x + threadIdx.x) >> 5;
    int lane = threadIdx.x & 31;
    if (warp >= B*L) return;
    int l = warp % L;
    int it = log_seqs[warp];
    int pos = (it != 0) ? (l + 1) : 0;
    float x0 = 0.f, x1 = 0.f;
    if (lane < D)
        x0 = item_emb[it*D + lane] * 7.0710678118654755f + pos_emb[pos*D + lane];
    if (lane + 32 < D)
        x1 = item_emb[it*D + lane + 32] * 7.0710678118654755f + pos_emb[pos*D + lane + 32];
    if (lane < D)      g_seqs[warp*D + lane]      = x0;
    if (lane + 32 < D) g_seqs[warp*D + lane + 32] = x1;
    float s = x0 + x1;
    #pragma unroll
    for (int o = 16; o; o >>= 1) s += __shfl_xor_sync(~0u, s, o);
    float m = s * (1.0f / D);
    float d0 = (lane < D)      ? x0 - m : 0.f;
    float d1 = (lane + 32 < D) ? x1 - m : 0.f;
    float v = d0*d0 + d1*d1;
    #pragma unroll
    for (int o = 16; o; o >>= 1) v += __shfl_xor_sync(~0u, v, o);
    float inv = rsqrtf(v * (1.0f / D) + 1e-8f);
    if (lane < D)      g_Qn[warp*D + lane]      = fmaf(d0*inv, g[lane],      bb[lane]);
    if (lane + 32 < D) g_Qn[warp*D + lane + 32] = fmaf(d1*inv, g[lane + 32], bb[lane + 32]);
}

// ---------------- QKV v5: CTA per (b, rowhalf, experthalf); 2x10 tile; dense stores ----------------
// smem (ull units): XQ @0 [2525], XS @2525 [2525], W @5050 [3750], bias floats @8800
#define QKV_SMEM_BYTES (8800*8 + 152*4)

__global__ void __launch_bounds__(256) k_qkv(const float* __restrict__ in_w,
                                             const float* __restrict__ in_b, int blk) {
    extern __shared__ __align__(16) ull sm[];
    ull* XQ = sm;                  // [i*101 + row] (row local 0..99)
    ull* XS = sm + 2525;
    ull* W  = sm + 5050;           // [i*150 + f]
    float* sbias = (float*)(sm + 8800);
    int b = blockIdx.x;
    int l0 = blockIdx.y * 100;
    int e0 = blockIdx.z * 5;
    int tid = threadIdx.x;
    bool act = tid < 250;
    int fg = act ? tid / 50 : 0;       // 0..4 (feature group / head)
    int rg = act ? tid - fg*50 : 0;    // 0..49 -> local rows rg, rg+50

    // stage X transposed (once)
    {
        const ull* gq = (const ull*)g_Qn   + ((size_t)b*L + l0)*25;
        const ull* gs = (const ull*)g_seqs + ((size_t)b*L + l0)*25;
        for (int o = tid; o < 2500; o += 256) {
            int row = o / 25, i = o - row*25;
            XQ[i*101 + row] = gq[o];
            XS[i*101 + row] = gs[o];
        }
    }

    #pragma unroll 1
    for (int e = e0; e < e0 + 5; ++e) {
        __syncthreads();
        {
            const ull* Wg = (const ull*)(in_w + (size_t)(blk*E + e)*7500);
            for (int o = tid; o < 3750; o += 256) {
                int f = o / 25, i = o - f*25;
                W[i*150 + f] = Wg[o];
            }
            for (int o = tid; o < 150; o += 256) sbias[o] = in_b[(blk*E + e)*150 + o];
        }
        __syncthreads();

        #pragma unroll 1
        for (int pass = 0; pass < 3; ++pass) {
            const ull* X = (pass == 0) ? XQ : XS;
            int f0 = pass*50 + fg*10;
            ull acc[2][10];
            #pragma unroll
            for (int r = 0; r < 2; ++r)
                #pragma unroll
                for (int j = 0; j < 10; ++j) acc[r][j] = 0ull;
            #pragma unroll
            for (int i = 0; i < 25; ++i) {
                ull x0 = X[i*101 + rg];
                ull x1 = X[i*101 + rg + 50];
                const ull* wp = W + i*150 + f0;   // uniform across warp -> broadcast
                #pragma unroll
                for (int j2 = 0; j2 < 5; ++j2) {
                    ulonglong2 w2 = *(const ulonglong2*)(wp + 2*j2);
                    FMA2(acc[0][2*j2],   w2.x, x0, acc[0][2*j2]);
                    FMA2(acc[0][2*j2+1], w2.y, x0, acc[0][2*j2+1]);
                    FMA2(acc[1][2*j2],   w2.x, x1, acc[1][2*j2]);
                    FMA2(acc[1][2*j2+1], w2.y, x1, acc[1][2*j2+1]);
                }
            }
            if (act) {
                float* arr = (pass == 0) ? g_q : (pass == 1) ? g_k : g_v;
                ull* dst = (ull*)arr + ((size_t)(b*E + e)*H + fg)*1000;
                #pragma unroll
                for (int r = 0; r < 2; ++r) {
                    int row = l0 + rg + 50*r;
                    #pragma unroll
                    for (int j2 = 0; j2 < 5; ++j2) {
                        float v0 = hadd2(acc[r][2*j2])   + sbias[f0 + 2*j2];
                        float v1 = hadd2(acc[r][2*j2+1]) + sbias[f0 + 2*j2 + 1];
                        dst[j2*200 + row] = pack2(v0, v1);   // dense across lanes
                    }
                }
            }
        }
    }
}

// ---------------- attention: 2 query rows per lane, gate folded in ----------------
__global__ void __launch_bounds__(128) k_attn() {
    int id = blockIdx.x;            // (b*E+e)*H + h
    int h = id % H; int be = id / H;
    __shared__ __align__(16) ull ks[1000];   // row-major [j*5 + d2]
    __shared__ __align__(16) ull vs[1000];
    {
        const ull* kb = (const ull*)g_k + (size_t)(be*H + h)*1000;   // [d2*200 + l]
        const ull* vb = (const ull*)g_v + (size_t)(be*H + h)*1000;
        for (int o = threadIdx.x; o < 1000; o += 128) {
            int d2 = o / 200, l = o - d2*200;
            ks[l*5 + d2] = kb[o];
            vs[l*5 + d2] = vb[o];
        }
    }
    __syncthreads();
    int w = threadIdx.x >> 5, lane = threadIdx.x & 31;
    int r0 = w*64 + lane*2, r1 = r0 + 1;
    bool valid = r0 < L;
    int rb = valid ? r0 : 0;
    const float scale = 0.31622776601683794f;   // 1/sqrt(10)
    ull q0[5], q1[5];
    {
        const ull* qb = (const ull*)g_q + (size_t)(be*H + h)*1000;
        #pragma unroll
        for (int d = 0; d < 5; ++d) {
            ulonglong2 qq = *(const ulonglong2*)(qb + d*200 + rb);   // rows r0, r1
            q0[d] = qq.x; q1[d] = qq.y;
        }
    }
    int jmax = w*64 + 64; if (jmax > L) jmax = L;
    float ps0 = 0.f, ps1 = 0.f;
    ull a0[5] = {0,0,0,0,0}, a1[5] = {0,0,0,0,0};
    #pragma unroll 2
    for (int j = 0; j < jmax; ++j) {
        const ull* kj = ks + j*5;
        const ull* vj = vs + j*5;
        ull s0 = 0ull, s1 = 0ull;
        #pragma unroll
        for (int d = 0; d < 5; ++d) {
            ull kd = kj[d];
            FMA2(s0, q0[d], kd, s0);
            FMA2(s1, q1[d], kd, s1);
        }
        float sc0 = hadd2(s0) * scale;
        float sc1 = hadd2(s1) * scale;
        float p0 = (j <= r0) ? __expf(sc0) : 0.f;
        float p1 = (j <= r1) ? __expf(sc1) : 0.f;
        ps0 += p0; ps1 += p1;
        ull pp0 = pack2(p0, p0), pp1 = pack2(p1, p1);
        #pragma unroll
        for (int d = 0; d < 5; ++d) {
            ull vd = vj[d];
            FMA2(a0[d], pp0, vd, a0[d]);
            FMA2(a1[d], pp1, vd, a1[d]);
        }
    }
    if (valid) {
        int b = be / E, e = be - b*E;
        float gt = g_gate[b*E + e];
        float i0 = gt / ps0, i1 = gt / ps1;
        ull* c0 = (ull*)g_ctx + ((size_t)be*L + r0)*25 + h*5;
        ull* c1 = (ull*)g_ctx + ((size_t)be*L + r1)*25 + h*5;
        #pragma unroll
        for (int d = 0; d < 5; ++d) {
            float lo, hi;
            unpk2(a0[d], lo, hi); c0[d] = pack2(lo*i0, hi*i0);
            unpk2(a1[d], lo, hi); c1[d] = pack2(lo*i1, hi*i1);
        }
    }
}

// ---------------- out-proj + bias-mix + residual + LN2 fused: CTA per (b, half) ----------------
__global__ void __launch_bounds__(256) k_combine(const float* __restrict__ out_w,
                                                 const float* __restrict__ out_b,
                                                 const float* __restrict__ ln_g,
                                                 const float* __restrict__ ln_b, int blk) {
    __shared__ __align__(16) ull CT[2525];   // transposed ctx [i*101 + row]; reused as SOUT
    __shared__ __align__(16) ull WT[1250];   // [i*50 + f] W[f][2i..2i+1]
    int b = blockIdx.x;
    int l0 = blockIdx.y * 100;
    int tid = threadIdx.x;
    bool act = tid < 250;
    int fg = tid / 50;           // 0..4
    int rg = tid - fg*50;        // rows rg, rg+50 (local)
    ull acc[2][10];
    #pragma unroll
    for (int r = 0; r < 2; ++r)
        #pragma unroll
        for (int j = 0; j < 10; ++j) acc[r][j] = 0ull;
    float bm[10];
    #pragma unroll
    for (int j = 0; j < 10; ++j) bm[j] = 0.f;

    for (int e = 0; e < E; ++e) {
        __syncthreads();
        {
            const ull* Wg = (const ull*)(out_w + (size_t)(blk*E + e)*2500);
            for (int o = tid; o < 1250; o += 256) {
                int f = o / 25, i = o - f*25;
                WT[i*50 + f] = Wg[o];
            }
            const ull* cg = (const ull*)g_ctx + ((size_t)(b*E + e)*L + l0)*25;
            for (int o = tid; o < 2500; o += 256) {
                int row = o / 25, i = o - row*25;
                CT[i*101 + row] = cg[o];
            }
        }
        float ge = g_gate[b*E + e];
        if (act) {
            #pragma unroll
            for (int j = 0; j < 10; ++j)
                bm[j] = fmaf(ge, out_b[(blk*E + e)*D + fg*10 + j], bm[j]);
        }
        __syncthreads();
        if (act) {
            #pragma unroll 5
            for (int i = 0; i < 25; ++i) {
                ull x0 = CT[i*101 + rg];
                ull x1 = CT[i*101 + rg + 50];
                const ull* wp = WT + i*50 + fg*10;
                #pragma unroll
                for (int j2 = 0; j2 < 5; ++j2) {
                    ulonglong2 w2 = *(const ulonglong2*)(wp + 2*j2);
                    FMA2(acc[0][2*j2],   w2.x, x0, acc[0][2*j2]);
                    FMA2(acc[0][2*j2+1], w2.y, x0, acc[0][2*j2+1]);
                    FMA2(acc[1][2*j2],   w2.x, x1, acc[1][2*j2]);
                    FMA2(acc[1][2*j2+1], w2.y, x1, acc[1][2*j2+1]);
                }
            }
        }
    }
    __syncthreads();
    if (act) {
        #pragma unroll
        for (int r = 0; r < 2; ++r) {
            int row = rg + 50*r;
            #pragma unroll
            for (int j2 = 0; j2 < 5; ++j2) {
                float v0 = hadd2(acc[r][2*j2])   + bm[2*j2];
                float v1 = hadd2(acc[r][2*j2+1]) + bm[2*j2+1];
                CT[row*25 + fg*5 + j2] = pack2(v0, v1);   // SOUT (gated sum + bias-mix)
            }
        }
    }
    __syncthreads();
    // fused: tmp = SOUT + Qn (residual); g_seqs = LN2(tmp)
    {
        int wid = tid >> 5, lane = tid & 31;
        float ga = 0.f, gb = 0.f, ba = 0.f, bbv = 0.f;
        if (lane < 25) {
            ga = ln_g[2*lane]; gb = ln_g[2*lane + 1];
            ba = ln_b[2*lane]; bbv = ln_b[2*lane + 1];
        }
        for (int r = wid; r < 100; r += 8) {
            size_t gro = ((size_t)b*L + l0 + r)*25 + lane;
            float a = 0.f, c = 0.f;
            if (lane < 25) {
                float s0, s1, q0, q1;
                unpk2(CT[r*25 + lane], s0, s1);
                unpk2(((const ull*)g_Qn)[gro], q0, q1);
                a = s0 + q0; c = s1 + q1;
            }
            float s = a + c;
            #pragma unroll
            for (int o = 16; o; o >>= 1) s += __shfl_xor_sync(~0u, s, o);
            float m = s * (1.0f / D);
            float da = (lane < 25) ? a - m : 0.f;
            float dc = (lane < 25) ? c - m : 0.f;
            float v = da*da + dc*dc;
            #pragma unroll
            for (int o = 16; o; o >>= 1) v += __shfl_xor_sync(~0u, v, o);
            float inv = rsqrtf(v * (1.0f / D) + 1e-8f);
            if (lane < 25) {
                float y0 = fmaf(da*inv, ga, ba);
                float y1 = fmaf(dc*inv, gb, bbv);
                ((ull*)g_seqs)[gro] = pack2(y0, y1);
            }
        }
    }
}

// ---------------- FFN + residual + LN1(next blk) fused: CTA per (b, half) ----------------
#define FFN_SMEM_BYTES (7550*8 + 104*4)

__global__ void __launch_bounds__(256) k_ffn(const float* __restrict__ f1_w, const float* __restrict__ f1_b,
                                             const float* __restrict__ f2_w, const float* __restrict__ f2_b,
                                             const float* __restrict__ ln_g, const float* __restrict__ ln_b,
                                             int blk, int has_next) {
    extern __shared__ __align__(16) ull sf[];
    ull* XT  = sf;            // [i*101 + row]; later reused as SOUT (row*25 + i)
    ull* HT  = sf + 2525;
    ull* W1T = sf + 5050;
    ull* W2T = sf + 6300;
    float* b1s = (float*)(sf + 7550);
    float* b2s = b1s + 50;
    int b = blockIdx.x;
    int l0 = blockIdx.y * 100;
    int tid = threadIdx.x;
    bool act = tid < 250;
    int fg = act ? tid / 50 : 0;
    int rg = act ? tid - fg*50 : 0;

    {
        const ull* gs = (const ull*)g_seqs + ((size_t)b*L + l0)*25;
        for (int o = tid; o < 2500; o += 256) {
            int row = o / 25, i = o - row*25;
            XT[i*101 + row] = gs[o];
        }
        const ull* W1g = (const ull*)(f1_w + (size_t)blk*2500);
        const ull* W2g = (const ull*)(f2_w + (size_t)blk*2500);
        for (int o = tid; o < 1250; o += 256) {
            int f = o / 25, i = o - f*25;
            W1T[i*50 + f] = W1g[o];
            W2T[i*50 + f] = W2g[o];
        }
        if (tid < 50) { b1s[tid] = f1_b[blk*D + tid]; b2s[tid] = f2_b[blk*D + tid]; }
    }
    __syncthreads();

    int f0 = fg*10;
    {
        ull acc[2][10];
        #pragma unroll
        for (int r = 0; r < 2; ++r)
            #pragma unroll
            for (int j = 0; j < 10; ++j) acc[r][j] = 0ull;
        #pragma unroll 5
        for (int i = 0; i < 25; ++i) {
            ull x0 = XT[i*101 + rg];
            ull x1 = XT[i*101 + rg + 50];
            const ull* wp = W1T + i*50 + f0;
            #pragma unroll
            for (int j2 = 0; j2 < 5; ++j2) {
                ulonglong2 w2 = *(const ulonglong2*)(wp + 2*j2);
                FMA2(acc[0][2*j2],   w2.x, x0, acc[0][2*j2]);
                FMA2(acc[0][2*j2+1], w2.y, x0, acc[0][2*j2+1]);
                FMA2(acc[1][2*j2],   w2.x, x1, acc[1][2*j2]);
                FMA2(acc[1][2*j2+1], w2.y, x1, acc[1][2*j2+1]);
            }
        }
        if (act) {
            #pragma unroll
            for (int r = 0; r < 2; ++r) {
                #pragma unroll
                for (int j2 = 0; j2 < 5; ++j2) {
                    float h0 = fmaxf(hadd2(acc[r][2*j2])   + b1s[f0 + 2*j2],     0.f);
                    float h1 = fmaxf(hadd2(acc[r][2*j2+1]) + b1s[f0 + 2*j2 + 1], 0.f);
                    HT[(fg*5 + j2)*101 + rg + 50*r] = pack2(h0, h1);
                }
            }
        }
    }
    __syncthreads();
    {
        ull acc[2][10];
        #pragma unroll
        for (int r = 0; r < 2; ++r)
            #pragma unroll
            for (int j = 0; j < 10; ++j) acc[r][j] = 0ull;
        #pragma unroll 5
        for (int i = 0; i < 25; ++i) {
            ull h0 = HT[i*101 + rg];
            ull h1 = HT[i*101 + rg + 50];
            const ull* wp = W2T + i*50 + f0;
            #pragma unroll
            for (int j2 = 0; j2 < 5; ++j2) {
                ulonglong2 w2 = *(const ulonglong2*)(wp + 2*j2);
                FMA2(acc[0][2*j2],   w2.x, h0, acc[0][2*j2]);
                FMA2(acc[0][2*j2+1], w2.y, h0, acc[0][2*j2+1]);
                FMA2(acc[1][2*j2],   w2.x, h1, acc[1][2*j2]);
                FMA2(acc[1][2*j2+1], w2.y, h1, acc[1][2*j2+1]);
            }
        }
        if (act) {
            #pragma unroll
            for (int r = 0; r < 2; ++r) {
                int row = rg + 50*r;
                #pragma unroll
                for (int j2 = 0; j2 < 5; ++j2) {
                    float o0 = hadd2(acc[r][2*j2])   + b2s[f0 + 2*j2];
                    float o1 = hadd2(acc[r][2*j2+1]) + b2s[f0 + 2*j2 + 1];
                    XT[row*25 + fg*5 + j2] = pack2(o0, o1);   // SOUT (ffn output, pre-residual)
                }
            }
        }
    }
    __syncthreads();
    // fused: x = SOUT + seqs (residual) -> g_seqs; g_Qn = LN1_next(x) when has_next
    {
        int wid = tid >> 5, lane = tid & 31;
        float ga = 0.f, gb = 0.f, ba = 0.f, bbv = 0.f;
        if (has_next && lane < 25) {
            ga = ln_g[2*lane]; gb = ln_g[2*lane + 1];
            ba = ln_b[2*lane]; bbv = ln_b[2*lane + 1];
        }
        for (int r = wid; r < 100; r += 8) {
            size_t gro = ((size_t)b*L + l0 + r)*25 + lane;
            float a = 0.f, c = 0.f;
            if (lane < 25) {
                float s0, s1, q0, q1;
                unpk2(XT[r*25 + lane], s0, s1);
                unpk2(((const ull*)g_seqs)[gro], q0, q1);
                a = s0 + q0; c = s1 + q1;
                ((ull*)g_seqs)[gro] = pack2(a, c);
            }
            if (has_next) {
                float s = a + c;
                #pragma unroll
                for (int o = 16; o; o >>= 1) s += __shfl_xor_sync(~0u, s, o);
                float m = s * (1.0f / D);
                float da = (lane < 25) ? a - m : 0.f;
                float dc = (lane < 25) ? c - m : 0.f;
                float v = da*da + dc*dc;
                #pragma unroll
                for (int o = 16; o; o >>= 1) v += __shfl_xor_sync(~0u, v, o);
                float inv = rsqrtf(v * (1.0f / D) + 1e-8f);
                if (lane < 25) {
                    float y0 = fmaf(da*inv, ga, ba);
                    float y1 = fmaf(dc*inv, gb, bbv);
                    ((ull*)g_Qn)[gro] = pack2(y0, y1);
                }
            }
        }
    }
}

// ---------------- final LN + pos/neg logits ----------------
__global__ void k_final(const float* __restrict__ lnf_g, const float* __restrict__ lnf_b,
                        const float* __restrict__ item_emb,
                        const int* __restrict__ pos_seqs, const int* __restrict__ neg_seqs,
                        float* __restrict__ out) {
    int warp = (blockIdx.x*blockDim.x + threadIdx.x) >> 5;
    int lane = threadIdx.x & 31;
    if (warp >= B*L) return;
    const float* x = g_seqs + warp*D;
    float x0 = (lane < D)      ? x[lane]      : 0.f;
    float x1 = (lane + 32 < D) ? x[lane + 32] : 0.f;
    float s = x0 + x1;
    #pragma unroll
    for (int o = 16; o; o >>= 1) s += __shfl_xor_sync(~0u, s, o);
    float m = s * (1.0f / D);
    float d0 = (lane < D)      ? x0 - m : 0.f;
    float d1 = (lane + 32 < D) ? x1 - m : 0.f;
    float v = d0*d0 + d1*d1;
    #pragma unroll
    for (int o = 16; o; o >>= 1) v += __shfl_xor_sync(~0u, v, o);
    float inv = rsqrtf(v * (1.0f / D) + 1e-8f);
    float f0 = (lane < D)      ? fmaf(d0*inv, lnf_g[lane],      lnf_b[lane])      : 0.f;
    float f1 = (lane + 32 < D) ? fmaf(d1*inv, lnf_g[lane + 32], lnf_b[lane + 32]) : 0.f;
    int ip = pos_seqs[warp], in_ = neg_seqs[warp];
    const float* pe = item_emb + (size_t)ip*D;
    const float* ne = item_emb + (size_t)in_*D;
    float dp = 0.f, dn = 0.f;
    if (lane < D)      { dp = f0*pe[lane];                 dn = f0*ne[lane]; }
    if (lane + 32 < D) { dp = fmaf(f1, pe[lane + 32], dp); dn = fmaf(f1, ne[lane + 32], dn); }
    #pragma unroll
    for (int o = 16; o; o >>= 1) {
        dp += __shfl_xor_sync(~0u, dp, o);
        dn += __shfl_xor_sync(~0u, dn, o);
    }
    if (lane == 0) { out[warp] = dp; out[B*L + warp] = dn; }
}

// ---------------- launch ----------------
extern "C" void kernel_launch(void* const* d_in, const int* in_sizes, int n_in,
                              void* d_out, int out_size) {
    const float* item_emb = (const float*)d_in[0];
    const float* pos_emb  = (const float*)d_in[1];
    const float* rW1      = (const float*)d_in[2];
    const float* rb1      = (const float*)d_in[3];
    const float* rW2      = (const float*)d_in[4];
    const float* rb2      = (const float*)d_in[5];
    const float* ln1_g    = (const float*)d_in[6];
    const float* ln1_b    = (const float*)d_in[7];
    const float* in_w     = (const float*)d_in[8];
    const float* in_b     = (const float*)d_in[9];
    const float* out_w    = (const float*)d_in[10];
    const float* out_b    = (const float*)d_in[11];
    const float* ln2_g    = (const float*)d_in[12];
    const float* ln2_b    = (const float*)d_in[13];
    const float* f1_w     = (const float*)d_in[14];
    const float* f1_b     = (const float*)d_in[15];
    const float* f2_w     = (const float*)d_in[16];
    const float* f2_b     = (const float*)d_in[17];
    const float* lnf_g    = (const float*)d_in[18];
    const float* lnf_b    = (const float*)d_in[19];
    const int*   log_seqs = (const int*)d_in[21];
    const int*   pos_seqs = (const int*)d_in[22];
    const int*   neg_seqs = (const int*)d_in[23];
    float* out = (float*)d_out;

    cudaFuncSetAttribute(k_qkv, cudaFuncAttributeMaxDynamicSharedMemorySize, QKV_SMEM_BYTES);
    cudaFuncSetAttribute(k_ffn, cudaFuncAttributeMaxDynamicSharedMemorySize, FFN_SMEM_BYTES);

    k_gate<<<B, 128>>>(item_emb, rW1, rb1, rW2, rb2, log_seqs);
    k_embed_ln<<<(B*L + 7)/8, 256>>>(item_emb, pos_emb, log_seqs, ln1_g, ln1_b);

    for (int blk = 0; blk < NB; ++blk) {
        k_qkv<<<dim3(B, 2, 2), 256, QKV_SMEM_BYTES>>>(in_w, in_b, blk);
        k_attn<<<B*E*H, 128>>>();
        k_combine<<<dim3(B, 2), 256>>>(out_w, out_b, ln2_g + blk*D, ln2_b + blk*D, blk);
        int has_next = (blk + 1 < NB) ? 1 : 0;
        k_ffn<<<dim3(B, 2), 256, FFN_SMEM_BYTES>>>(f1_w, f1_b, f2_w, f2_b,
                                                   ln1_g + (blk+1 < NB ? (blk+1)*D : 0),
                                                   ln1_b + (blk+1 < NB ? (blk+1)*D : 0),
                                                   blk, has_next);
    }

    k_final<<<(B*L + 7)/8, 256>>>(lnf_g, lnf_b, item_emb, pos_seqs, neg_seqs, out);
}

// round 16
// speedup vs baseline: 1.3491x; 1.1707x over previous
#include <cuda_runtime.h>

#define B 128
#define L 200
#define D 50
#define H 5
#define E 10
#define NB 2
#define DH 10

typedef unsigned long long ull;

#define FMA2(d,a,b,c) asm("fma.rn.f32x2 %0, %1, %2, %3;" : "=l"(d) : "l"(a), "l"(b), "l"(c))
#define MUL2(d,a,b)   asm("mul.rn.f32x2 %0, %1, %2;"     : "=l"(d) : "l"(a), "l"(b))

__device__ __forceinline__ float hadd2(ull v) {
    float lo, hi; asm("mov.b64 {%0,%1}, %2;" : "=f"(lo), "=f"(hi) : "l"(v)); return lo + hi;
}
__device__ __forceinline__ ull pack2(float a, float b) {
    ull r; asm("mov.b64 %0, {%1,%2};" : "=l"(r) : "f"(a), "f"(b)); return r;
}
__device__ __forceinline__ void unpk2(ull v, float& lo, float& hi) {
    asm("mov.b64 {%0,%1}, %2;" : "=f"(lo), "=f"(hi) : "l"(v));
}

// ---------------- scratch (device globals; allocation-free) ----------------
__device__ __align__(16) float g_seqs[B*L*D];
__device__ __align__(16) float g_Qn  [B*L*D];
__device__ __align__(16) float g_gate[B*E];
// q/k/v component-major: ull index ((be*H + h)*5 + d2)*200 + l   (d2 = dh pair)
__device__ __align__(16) float g_q   [B*E*H*L*DH];
__device__ __align__(16) float g_k   [B*E*H*L*DH];
__device__ __align__(16) float g_v   [B*E*H*L*DH];
__device__ __align__(16) float g_ctx [B*E*L*D];      // [be, l, d]  (gate pre-folded)

// ---------------- gate MLP ----------------
__global__ void k_gate(const float* __restrict__ item_emb,
                       const float* __restrict__ rW1, const float* __restrict__ rb1,
                       const float* __restrict__ rW2, const float* __restrict__ rb2,
                       const int* __restrict__ log_seqs) {
    __shared__ float mean[D];
    __shared__ float h[100];
    __shared__ float logit[E];
    int b = blockIdx.x, t = threadIdx.x;
    if (t < D) {
        float acc = 0.f;
        for (int l = 0; l < L; ++l) {
            int it = log_seqs[b*L + l];
            acc += item_emb[it*D + t];
        }
        mean[t] = acc * (7.0710678118654755f / 200.0f);
    }
    __syncthreads();
    if (t < 100) {
        float acc = rb1[t];
        #pragma unroll
        for (int d = 0; d < D; ++d) acc = fmaf(mean[d], rW1[t*D + d], acc);
        h[t] = fmaxf(acc, 0.f);
    }
    __syncthreads();
    if (t < E) {
        float acc = rb2[t];
        #pragma unroll
        for (int j = 0; j < 100; ++j) acc = fmaf(h[j], rW2[t*100 + j], acc);
        logit[t] = acc;
    }
    __syncthreads();
    if (t == 0) {
        float m = -1e30f;
        #pragma unroll
        for (int e = 0; e < E; ++e) m = fmaxf(m, logit[e]);
        float s = 0.f; float ex[E];
        #pragma unroll
        for (int e = 0; e < E; ++e) { ex[e] = expf(logit[e] - m); s += ex[e]; }
        float inv = 1.0f / s;
        #pragma unroll
        for (int e = 0; e < E; ++e) g_gate[b*E + e] = ex[e] * inv;
    }
}

// ---------------- embedding + positional + LN1(blk0): warp per row ----------------
__global__ void k_embed_ln(const float* __restrict__ item_emb,
                           const float* __restrict__ pos_emb,
                           const int* __restrict__ log_seqs,
                           const float* __restrict__ g, const float* __restrict__ bb) {
    int warp = (blockIdx.x*blockDim.x + threadIdx.x) >> 5;
    int lane = threadIdx.x & 31;
    if (warp >= B*L) return;
    int l = warp % L;
    int it = log_seqs[warp];
    int pos = (it != 0) ? (l + 1) : 0;
    float x0 = 0.f, x1 = 0.f;
    if (lane < D)
        x0 = item_emb[it*D + lane] * 7.0710678118654755f + pos_emb[pos*D + lane];
    if (lane + 32 < D)
        x1 = item_emb[it*D + lane + 32] * 7.0710678118654755f + pos_emb[pos*D + lane + 32];
    if (lane < D)      g_seqs[warp*D + lane]      = x0;
    if (lane + 32 < D) g_seqs[warp*D + lane + 32] = x1;
    float s = x0 + x1;
    #pragma unroll
    for (int o = 16; o; o >>= 1) s += __shfl_xor_sync(~0u, s, o);
    float m = s * (1.0f / D);
    float d0 = (lane < D)      ? x0 - m : 0.f;
    float d1 = (lane + 32 < D) ? x1 - m : 0.f;
    float v = d0*d0 + d1*d1;
    #pragma unroll
    for (int o = 16; o; o >>= 1) v += __shfl_xor_sync(~0u, v, o);
    float inv = rsqrtf(v * (1.0f / D) + 1e-8f);
    if (lane < D)      g_Qn[warp*D + lane]      = fmaf(d0*inv, g[lane],      bb[lane]);
    if (lane + 32 < D) g_Qn[warp*D + lane + 32] = fmaf(d1*inv, g[lane + 32], bb[lane + 32]);
}

// ---------------- QKV v5: CTA per (b, rowhalf, experthalf); 2x10 tile; dense stores ----------------
// smem (ull units): XQ @0 [2525], XS @2525 [2525], W @5050 [3750], bias floats @8800
#define QKV_SMEM_BYTES (8800*8 + 152*4)

__global__ void __launch_bounds__(256) k_qkv(const float* __restrict__ in_w,
                                             const float* __restrict__ in_b, int blk) {
    extern __shared__ __align__(16) ull sm[];
    ull* XQ = sm;                  // [i*101 + row] (row local 0..99)
    ull* XS = sm + 2525;
    ull* W  = sm + 5050;           // [i*150 + f]
    float* sbias = (float*)(sm + 8800);
    int b = blockIdx.x;
    int l0 = blockIdx.y * 100;
    int e0 = blockIdx.z * 5;
    int tid = threadIdx.x;
    bool act = tid < 250;
    int fg = act ? tid / 50 : 0;       // 0..4 (feature group / head)
    int rg = act ? tid - fg*50 : 0;    // 0..49 -> local rows rg, rg+50

    // stage X transposed (once)
    {
        const ull* gq = (const ull*)g_Qn   + ((size_t)b*L + l0)*25;
        const ull* gs = (const ull*)g_seqs + ((size_t)b*L + l0)*25;
        for (int o = tid; o < 2500; o += 256) {
            int row = o / 25, i = o - row*25;
            XQ[i*101 + row] = gq[o];
            XS[i*101 + row] = gs[o];
        }
    }

    #pragma unroll 1
    for (int e = e0; e < e0 + 5; ++e) {
        __syncthreads();
        {
            const ull* Wg = (const ull*)(in_w + (size_t)(blk*E + e)*7500);
            for (int o = tid; o < 3750; o += 256) {
                int f = o / 25, i = o - f*25;
                W[i*150 + f] = Wg[o];
            }
            for (int o = tid; o < 150; o += 256) sbias[o] = in_b[(blk*E + e)*150 + o];
        }
        __syncthreads();

        #pragma unroll 1
        for (int pass = 0; pass < 3; ++pass) {
            const ull* X = (pass == 0) ? XQ : XS;
            int f0 = pass*50 + fg*10;
            ull acc[2][10];
            #pragma unroll
            for (int r = 0; r < 2; ++r)
                #pragma unroll
                for (int j = 0; j < 10; ++j) acc[r][j] = 0ull;
            #pragma unroll
            for (int i = 0; i < 25; ++i) {
                ull x0 = X[i*101 + rg];
                ull x1 = X[i*101 + rg + 50];
                const ull* wp = W + i*150 + f0;   // uniform across warp -> broadcast
                #pragma unroll
                for (int j2 = 0; j2 < 5; ++j2) {
                    ulonglong2 w2 = *(const ulonglong2*)(wp + 2*j2);
                    FMA2(acc[0][2*j2],   w2.x, x0, acc[0][2*j2]);
                    FMA2(acc[0][2*j2+1], w2.y, x0, acc[0][2*j2+1]);
                    FMA2(acc[1][2*j2],   w2.x, x1, acc[1][2*j2]);
                    FMA2(acc[1][2*j2+1], w2.y, x1, acc[1][2*j2+1]);
                }
            }
            if (act) {
                float* arr = (pass == 0) ? g_q : (pass == 1) ? g_k : g_v;
                ull* dst = (ull*)arr + ((size_t)(b*E + e)*H + fg)*1000;
                #pragma unroll
                for (int r = 0; r < 2; ++r) {
                    int row = l0 + rg + 50*r;
                    #pragma unroll
                    for (int j2 = 0; j2 < 5; ++j2) {
                        float v0 = hadd2(acc[r][2*j2])   + sbias[f0 + 2*j2];
                        float v1 = hadd2(acc[r][2*j2+1]) + sbias[f0 + 2*j2 + 1];
                        dst[j2*200 + row] = pack2(v0, v1);   // dense across lanes
                    }
                }
            }
        }
    }
}

// ---------------- attention: causal-balanced warp split {0,8,72,136,200} ----------------
__global__ void __launch_bounds__(128) k_attn() {
    int id = blockIdx.x;            // (b*E+e)*H + h
    int h = id % H; int be = id / H;
    __shared__ __align__(16) ull ks[1000];   // row-major [j*5 + d2]
    __shared__ __align__(16) ull vs[1000];
    {
        const ull* kb = (const ull*)g_k + (size_t)(be*H + h)*1000;   // [d2*200 + l]
        const ull* vb = (const ull*)g_v + (size_t)(be*H + h)*1000;
        for (int o = threadIdx.x; o < 1000; o += 128) {
            int d2 = o / 200, l = o - d2*200;
            ks[l*5 + d2] = kb[o];
            vs[l*5 + d2] = vb[o];
        }
    }
    __syncthreads();
    int w = threadIdx.x >> 5, lane = threadIdx.x & 31;
    // causal-balanced split: minimizes sum of per-warp jmax
    const int wbase = (w == 0) ? 0 : (w == 1) ? 8 : (w == 2) ? 72 : 136;
    const int wend  = (w == 0) ? 8 : (w == 1) ? 72 : (w == 2) ? 136 : 200;
    int nl = (wend - wbase) >> 1;           // active lanes: 4 or 32
    bool valid = lane < nl;
    int li = valid ? lane : (nl - 1);
    int r0 = wbase + 2*li, r1 = r0 + 1;
    const float scale = 0.31622776601683794f;   // 1/sqrt(10)
    ull q0[5], q1[5];
    {
        const ull* qb = (const ull*)g_q + (size_t)(be*H + h)*1000;
        ull sc2 = pack2(scale, scale);
        #pragma unroll
        for (int d = 0; d < 5; ++d) {
            ulonglong2 qq = *(const ulonglong2*)(qb + d*200 + r0);   // rows r0, r1
            MUL2(q0[d], qq.x, sc2);     // pre-scale q by 1/sqrt(dh)
            MUL2(q1[d], qq.y, sc2);
        }
    }
    int jmax = wend;
    float ps0 = 0.f, ps1 = 0.f;
    ull a0[5] = {0,0,0,0,0}, a1[5] = {0,0,0,0,0};
    #pragma unroll 2
    for (int j = 0; j < jmax; ++j) {
        const ull* kj = ks + j*5;
        const ull* vj = vs + j*5;
        ull s0 = 0ull, s1 = 0ull;
        #pragma unroll
        for (int d = 0; d < 5; ++d) {
            ull kd = kj[d];
            FMA2(s0, q0[d], kd, s0);
            FMA2(s1, q1[d], kd, s1);
        }
        float sc0 = hadd2(s0);
        float sc1 = hadd2(s1);
        float p0 = (j <= r0) ? __expf(sc0) : 0.f;
        float p1 = (j <= r1) ? __expf(sc1) : 0.f;
        ps0 += p0; ps1 += p1;
        ull pp0 = pack2(p0, p0), pp1 = pack2(p1, p1);
        #pragma unroll
        for (int d = 0; d < 5; ++d) {
            ull vd = vj[d];
            FMA2(a0[d], pp0, vd, a0[d]);
            FMA2(a1[d], pp1, vd, a1[d]);
        }
    }
    if (valid) {
        int b = be / E, e = be - b*E;
        float gt = g_gate[b*E + e];
        float i0 = gt / ps0, i1 = gt / ps1;
        ull* c0 = (ull*)g_ctx + ((size_t)be*L + r0)*25 + h*5;
        ull* c1 = (ull*)g_ctx + ((size_t)be*L + r1)*25 + h*5;
        #pragma unroll
        for (int d = 0; d < 5; ++d) {
            float lo, hi;
            unpk2(a0[d], lo, hi); c0[d] = pack2(lo*i0, hi*i0);
            unpk2(a1[d], lo, hi); c1[d] = pack2(lo*i1, hi*i1);
        }
    }
}

// ---------------- out-proj + bias-mix + residual + LN2 fused: CTA per (b, half) ----------------
__global__ void __launch_bounds__(256) k_combine(const float* __restrict__ out_w,
                                                 const float* __restrict__ out_b,
                                                 const float* __restrict__ ln_g,
                                                 const float* __restrict__ ln_b, int blk) {
    __shared__ __align__(16) ull CT[2525];   // transposed ctx [i*101 + row]; reused as SOUT
    __shared__ __align__(16) ull WT[1250];   // [i*50 + f] W[f][2i..2i+1]
    int b = blockIdx.x;
    int l0 = blockIdx.y * 100;
    int tid = threadIdx.x;
    bool act = tid < 250;
    int fg = tid / 50;           // 0..4
    int rg = tid - fg*50;        // rows rg, rg+50 (local)
    ull acc[2][10];
    #pragma unroll
    for (int r = 0; r < 2; ++r)
        #pragma unroll
        for (int j = 0; j < 10; ++j) acc[r][j] = 0ull;
    float bm[10];
    #pragma unroll
    for (int j = 0; j < 10; ++j) bm[j] = 0.f;

    for (int e = 0; e < E; ++e) {
        __syncthreads();
        {
            const ull* Wg = (const ull*)(out_w + (size_t)(blk*E + e)*2500);
            for (int o = tid; o < 1250; o += 256) {
                int f = o / 25, i = o - f*25;
                WT[i*50 + f] = Wg[o];
            }
            const ull* cg = (const ull*)g_ctx + ((size_t)(b*E + e)*L + l0)*25;
            for (int o = tid; o < 2500; o += 256) {
                int row = o / 25, i = o - row*25;
                CT[i*101 + row] = cg[o];
            }
        }
        float ge = g_gate[b*E + e];
        if (act) {
            #pragma unroll
            for (int j = 0; j < 10; ++j)
                bm[j] = fmaf(ge, out_b[(blk*E + e)*D + fg*10 + j], bm[j]);
        }
        __syncthreads();
        if (act) {
            #pragma unroll 5
            for (int i = 0; i < 25; ++i) {
                ull x0 = CT[i*101 + rg];
                ull x1 = CT[i*101 + rg + 50];
                const ull* wp = WT + i*50 + fg*10;
                #pragma unroll
                for (int j2 = 0; j2 < 5; ++j2) {
                    ulonglong2 w2 = *(const ulonglong2*)(wp + 2*j2);
                    FMA2(acc[0][2*j2],   w2.x, x0, acc[0][2*j2]);
                    FMA2(acc[0][2*j2+1], w2.y, x0, acc[0][2*j2+1]);
                    FMA2(acc[1][2*j2],   w2.x, x1, acc[1][2*j2]);
                    FMA2(acc[1][2*j2+1], w2.y, x1, acc[1][2*j2+1]);
                }
            }
        }
    }
    __syncthreads();
    if (act) {
        #pragma unroll
        for (int r = 0; r < 2; ++r) {
            int row = rg + 50*r;
            #pragma unroll
            for (int j2 = 0; j2 < 5; ++j2) {
                float v0 = hadd2(acc[r][2*j2])   + bm[2*j2];
                float v1 = hadd2(acc[r][2*j2+1]) + bm[2*j2+1];
                CT[row*25 + fg*5 + j2] = pack2(v0, v1);   // SOUT (gated sum + bias-mix)
            }
        }
    }
    __syncthreads();
    // fused: tmp = SOUT + Qn (residual); g_seqs = LN2(tmp)
    {
        int wid = tid >> 5, lane = tid & 31;
        float ga = 0.f, gb = 0.f, ba = 0.f, bbv = 0.f;
        if (lane < 25) {
            ga = ln_g[2*lane]; gb = ln_g[2*lane + 1];
            ba = ln_b[2*lane]; bbv = ln_b[2*lane + 1];
        }
        for (int r = wid; r < 100; r += 8) {
            size_t gro = ((size_t)b*L + l0 + r)*25 + lane;
            float a = 0.f, c = 0.f;
            if (lane < 25) {
                float s0, s1, q0, q1;
                unpk2(CT[r*25 + lane], s0, s1);
                unpk2(((const ull*)g_Qn)[gro], q0, q1);
                a = s0 + q0; c = s1 + q1;
            }
            float s = a + c;
            #pragma unroll
            for (int o = 16; o; o >>= 1) s += __shfl_xor_sync(~0u, s, o);
            float m = s * (1.0f / D);
            float da = (lane < 25) ? a - m : 0.f;
            float dc = (lane < 25) ? c - m : 0.f;
            float v = da*da + dc*dc;
            #pragma unroll
            for (int o = 16; o; o >>= 1) v += __shfl_xor_sync(~0u, v, o);
            float inv = rsqrtf(v * (1.0f / D) + 1e-8f);
            if (lane < 25) {
                float y0 = fmaf(da*inv, ga, ba);
                float y1 = fmaf(dc*inv, gb, bbv);
                ((ull*)g_seqs)[gro] = pack2(y0, y1);
            }
        }
    }
}

// ---------------- FFN + residual + LN1(next blk) fused: CTA per (b, half) ----------------
#define FFN_SMEM_BYTES (7550*8 + 104*4)

__global__ void __launch_bounds__(256) k_ffn(const float* __restrict__ f1_w, const float* __restrict__ f1_b,
                                             const float* __restrict__ f2_w, const float* __restrict__ f2_b,
                                             const float* __restrict__ ln_g, const float* __restrict__ ln_b,
                                             int blk, int has_next) {
    extern __shared__ __align__(16) ull sf[];
    ull* XT  = sf;            // [i*101 + row]; later reused as SOUT (row*25 + i)
    ull* HT  = sf + 2525;
    ull* W1T = sf + 5050;
    ull* W2T = sf + 6300;
    float* b1s = (float*)(sf + 7550);
    float* b2s = b1s + 50;
    int b = blockIdx.x;
    int l0 = blockIdx.y * 100;
    int tid = threadIdx.x;
    bool act = tid < 250;
    int fg = act ? tid / 50 : 0;
    int rg = act ? tid - fg*50 : 0;

    {
        const ull* gs = (const ull*)g_seqs + ((size_t)b*L + l0)*25;
        for (int o = tid; o < 2500; o += 256) {
            int row = o / 25, i = o - row*25;
            XT[i*101 + row] = gs[o];
        }
        const ull* W1g = (const ull*)(f1_w + (size_t)blk*2500);
        const ull* W2g = (const ull*)(f2_w + (size_t)blk*2500);
        for (int o = tid; o < 1250; o += 256) {
            int f = o / 25, i = o - f*25;
            W1T[i*50 + f] = W1g[o];
            W2T[i*50 + f] = W2g[o];
        }
        if (tid < 50) { b1s[tid] = f1_b[blk*D + tid]; b2s[tid] = f2_b[blk*D + tid]; }
    }
    __syncthreads();

    int f0 = fg*10;
    {
        ull acc[2][10];
        #pragma unroll
        for (int r = 0; r < 2; ++r)
            #pragma unroll
            for (int j = 0; j < 10; ++j) acc[r][j] = 0ull;
        #pragma unroll 5
        for (int i = 0; i < 25; ++i) {
            ull x0 = XT[i*101 + rg];
            ull x1 = XT[i*101 + rg + 50];
            const ull* wp = W1T + i*50 + f0;
            #pragma unroll
            for (int j2 = 0; j2 < 5; ++j2) {
                ulonglong2 w2 = *(const ulonglong2*)(wp + 2*j2);
                FMA2(acc[0][2*j2],   w2.x, x0, acc[0][2*j2]);
                FMA2(acc[0][2*j2+1], w2.y, x0, acc[0][2*j2+1]);
                FMA2(acc[1][2*j2],   w2.x, x1, acc[1][2*j2]);
                FMA2(acc[1][2*j2+1], w2.y, x1, acc[1][2*j2+1]);
            }
        }
        if (act) {
            #pragma unroll
            for (int r = 0; r < 2; ++r) {
                #pragma unroll
                for (int j2 = 0; j2 < 5; ++j2) {
                    float h0 = fmaxf(hadd2(acc[r][2*j2])   + b1s[f0 + 2*j2],     0.f);
                    float h1 = fmaxf(hadd2(acc[r][2*j2+1]) + b1s[f0 + 2*j2 + 1], 0.f);
                    HT[(fg*5 + j2)*101 + rg + 50*r] = pack2(h0, h1);
                }
            }
        }
    }
    __syncthreads();
    {
        ull acc[2][10];
        #pragma unroll
        for (int r = 0; r < 2; ++r)
            #pragma unroll
            for (int j = 0; j < 10; ++j) acc[r][j] = 0ull;
        #pragma unroll 5
        for (int i = 0; i < 25; ++i) {
            ull h0 = HT[i*101 + rg];
            ull h1 = HT[i*101 + rg + 50];
            const ull* wp = W2T + i*50 + f0;
            #pragma unroll
            for (int j2 = 0; j2 < 5; ++j2) {
                ulonglong2 w2 = *(const ulonglong2*)(wp + 2*j2);
                FMA2(acc[0][2*j2],   w2.x, h0, acc[0][2*j2]);
                FMA2(acc[0][2*j2+1], w2.y, h0, acc[0][2*j2+1]);
                FMA2(acc[1][2*j2],   w2.x, h1, acc[1][2*j2]);
                FMA2(acc[1][2*j2+1], w2.y, h1, acc[1][2*j2+1]);
            }
        }
        if (act) {
            #pragma unroll
            for (int r = 0; r < 2; ++r) {
                int row = rg + 50*r;
                #pragma unroll
                for (int j2 = 0; j2 < 5; ++j2) {
                    float o0 = hadd2(acc[r][2*j2])   + b2s[f0 + 2*j2];
                    float o1 = hadd2(acc[r][2*j2+1]) + b2s[f0 + 2*j2 + 1];
                    XT[row*25 + fg*5 + j2] = pack2(o0, o1);   // SOUT (ffn output, pre-residual)
                }
            }
        }
    }
    __syncthreads();
    // fused: x = SOUT + seqs (residual) -> g_seqs; g_Qn = LN1_next(x) when has_next
    {
        int wid = tid >> 5, lane = tid & 31;
        float ga = 0.f, gb = 0.f, ba = 0.f, bbv = 0.f;
        if (has_next && lane < 25) {
            ga = ln_g[2*lane]; gb = ln_g[2*lane + 1];
            ba = ln_b[2*lane]; bbv = ln_b[2*lane + 1];
        }
        for (int r = wid; r < 100; r += 8) {
            size_t gro = ((size_t)b*L + l0 + r)*25 + lane;
            float a = 0.f, c = 0.f;
            if (lane < 25) {
                float s0, s1, q0, q1;
                unpk2(XT[r*25 + lane], s0, s1);
                unpk2(((const ull*)g_seqs)[gro], q0, q1);
                a = s0 + q0; c = s1 + q1;
                ((ull*)g_seqs)[gro] = pack2(a, c);
            }
            if (has_next) {
                float s = a + c;
                #pragma unroll
                for (int o = 16; o; o >>= 1) s += __shfl_xor_sync(~0u, s, o);
                float m = s * (1.0f / D);
                float da = (lane < 25) ? a - m : 0.f;
                float dc = (lane < 25) ? c - m : 0.f;
                float v = da*da + dc*dc;
                #pragma unroll
                for (int o = 16; o; o >>= 1) v += __shfl_xor_sync(~0u, v, o);
                float inv = rsqrtf(v * (1.0f / D) + 1e-8f);
                if (lane < 25) {
                    float y0 = fmaf(da*inv, ga, ba);
                    float y1 = fmaf(dc*inv, gb, bbv);
                    ((ull*)g_Qn)[gro] = pack2(y0, y1);
                }
            }
        }
    }
}

// ---------------- final LN + pos/neg logits ----------------
__global__ void k_final(const float* __restrict__ lnf_g, const float* __restrict__ lnf_b,
                        const float* __restrict__ item_emb,
                        const int* __restrict__ pos_seqs, const int* __restrict__ neg_seqs,
                        float* __restrict__ out) {
    int warp = (blockIdx.x*blockDim.x + threadIdx.x) >> 5;
    int lane = threadIdx.x & 31;
    if (warp >= B*L) return;
    const float* x = g_seqs + warp*D;
    float x0 = (lane < D)      ? x[lane]      : 0.f;
    float x1 = (lane + 32 < D) ? x[lane + 32] : 0.f;
    float s = x0 + x1;
    #pragma unroll
    for (int o = 16; o; o >>= 1) s += __shfl_xor_sync(~0u, s, o);
    float m = s * (1.0f / D);
    float d0 = (lane < D)      ? x0 - m : 0.f;
    float d1 = (lane + 32 < D) ? x1 - m : 0.f;
    float v = d0*d0 + d1*d1;
    #pragma unroll
    for (int o = 16; o; o >>= 1) v += __shfl_xor_sync(~0u, v, o);
    float inv = rsqrtf(v * (1.0f / D) + 1e-8f);
    float f0 = (lane < D)      ? fmaf(d0*inv, lnf_g[lane],      lnf_b[lane])      : 0.f;
    float f1 = (lane + 32 < D) ? fmaf(d1*inv, lnf_g[lane + 32], lnf_b[lane + 32]) : 0.f;
    int ip = pos_seqs[warp], in_ = neg_seqs[warp];
    const float* pe = item_emb + (size_t)ip*D;
    const float* ne = item_emb + (size_t)in_*D;
    float dp = 0.f, dn = 0.f;
    if (lane < D)      { dp = f0*pe[lane];                 dn = f0*ne[lane]; }
    if (lane + 32 < D) { dp = fmaf(f1, pe[lane + 32], dp); dn = fmaf(f1, ne[lane + 32], dn); }
    #pragma unroll
    for (int o = 16; o; o >>= 1) {
        dp += __shfl_xor_sync(~0u, dp, o);
        dn += __shfl_xor_sync(~0u, dn, o);
    }
    if (lane == 0) { out[warp] = dp; out[B*L + warp] = dn; }
}

// ---------------- launch ----------------
extern "C" void kernel_launch(void* const* d_in, const int* in_sizes, int n_in,
                              void* d_out, int out_size) {
    const float* item_emb = (const float*)d_in[0];
    const float* pos_emb  = (const float*)d_in[1];
    const float* rW1      = (const float*)d_in[2];
    const float* rb1      = (const float*)d_in[3];
    const float* rW2      = (const float*)d_in[4];
    const float* rb2      = (const float*)d_in[5];
    const float* ln1_g    = (const float*)d_in[6];
    const float* ln1_b    = (const float*)d_in[7];
    const float* in_w     = (const float*)d_in[8];
    const float* in_b     = (const float*)d_in[9];
    const float* out_w    = (const float*)d_in[10];
    const float* out_b    = (const float*)d_in[11];
    const float* ln2_g    = (const float*)d_in[12];
    const float* ln2_b    = (const float*)d_in[13];
    const float* f1_w     = (const float*)d_in[14];
    const float* f1_b     = (const float*)d_in[15];
    const float* f2_w     = (const float*)d_in[16];
    const float* f2_b     = (const float*)d_in[17];
    const float* lnf_g    = (const float*)d_in[18];
    const float* lnf_b    = (const float*)d_in[19];
    const int*   log_seqs = (const int*)d_in[21];
    const int*   pos_seqs = (const int*)d_in[22];
    const int*   neg_seqs = (const int*)d_in[23];
    float* out = (float*)d_out;

    cudaFuncSetAttribute(k_qkv, cudaFuncAttributeMaxDynamicSharedMemorySize, QKV_SMEM_BYTES);
    cudaFuncSetAttribute(k_ffn, cudaFuncAttributeMaxDynamicSharedMemorySize, FFN_SMEM_BYTES);

    k_gate<<<B, 128>>>(item_emb, rW1, rb1, rW2, rb2, log_seqs);
    k_embed_ln<<<(B*L + 7)/8, 256>>>(item_emb, pos_emb, log_seqs, ln1_g, ln1_b);

    for (int blk = 0; blk < NB; ++blk) {
        k_qkv<<<dim3(B, 2, 2), 256, QKV_SMEM_BYTES>>>(in_w, in_b, blk);
        k_attn<<<B*E*H, 128>>>();
        k_combine<<<dim3(B, 2), 256>>>(out_w, out_b, ln2_g + blk*D, ln2_b + blk*D, blk);
        int has_next = (blk + 1 < NB) ? 1 : 0;
        k_ffn<<<dim3(B, 2), 256, FFN_SMEM_BYTES>>>(f1_w, f1_b, f2_w, f2_b,
                                                   ln1_g + (blk+1 < NB ? (blk+1)*D : 0),
                                                   ln1_b + (blk+1 < NB ? (blk+1)*D : 0),
                                                   blk, has_next);
    }

    k_final<<<(B*L + 7)/8, 256>>>(lnf_g, lnf_b, item_emb, pos_seqs, neg_seqs, out);
}

// round 17
// speedup vs baseline: 1.3700x; 1.0155x over previous
#include <cuda_runtime.h>

#define B 128
#define L 200
#define D 50
#define H 5
#define E 10
#define NB 2
#define DH 10

typedef unsigned long long ull;

#define FMA2(d,a,b,c) asm("fma.rn.f32x2 %0, %1, %2, %3;" : "=l"(d) : "l"(a), "l"(b), "l"(c))
#define MUL2(d,a,b)   asm("mul.rn.f32x2 %0, %1, %2;"     : "=l"(d) : "l"(a), "l"(b))

__device__ __forceinline__ float hadd2(ull v) {
    float lo, hi; asm("mov.b64 {%0,%1}, %2;" : "=f"(lo), "=f"(hi) : "l"(v)); return lo + hi;
}
__device__ __forceinline__ ull pack2(float a, float b) {
    ull r; asm("mov.b64 %0, {%1,%2};" : "=l"(r) : "f"(a), "f"(b)); return r;
}
__device__ __forceinline__ void unpk2(ull v, float& lo, float& hi) {
    asm("mov.b64 {%0,%1}, %2;" : "=f"(lo), "=f"(hi) : "l"(v));
}
__device__ __forceinline__ float ex2f(float x) {
    float r; asm("ex2.approx.ftz.f32 %0, %1;" : "=f"(r) : "f"(x)); return r;
}

// ---------------- scratch (device globals; allocation-free) ----------------
__device__ __align__(16) float g_seqs[B*L*D];
__device__ __align__(16) float g_Qn  [B*L*D];
__device__ __align__(16) float g_gate[B*E];
// q/k/v component-major: ull index ((be*H + h)*5 + d2)*200 + l   (d2 = dh pair)
__device__ __align__(16) float g_q   [B*E*H*L*DH];
__device__ __align__(16) float g_k   [B*E*H*L*DH];
__device__ __align__(16) float g_v   [B*E*H*L*DH];
__device__ __align__(16) float g_ctx [B*E*L*D];      // [be, l, d]  (gate pre-folded)

// ---------------- gate MLP ----------------
__global__ void k_gate(const float* __restrict__ item_emb,
                       const float* __restrict__ rW1, const float* __restrict__ rb1,
                       const float* __restrict__ rW2, const float* __restrict__ rb2,
                       const int* __restrict__ log_seqs) {
    __shared__ float mean[D];
    __shared__ float h[100];
    __shared__ float logit[E];
    int b = blockIdx.x, t = threadIdx.x;
    if (t < D) {
        float acc = 0.f;
        for (int l = 0; l < L; ++l) {
            int it = log_seqs[b*L + l];
            acc += item_emb[it*D + t];
        }
        mean[t] = acc * (7.0710678118654755f / 200.0f);
    }
    __syncthreads();
    if (t < 100) {
        float acc = rb1[t];
        #pragma unroll
        for (int d = 0; d < D; ++d) acc = fmaf(mean[d], rW1[t*D + d], acc);
        h[t] = fmaxf(acc, 0.f);
    }
    __syncthreads();
    if (t < E) {
        float acc = rb2[t];
        #pragma unroll
        for (int j = 0; j < 100; ++j) acc = fmaf(h[j], rW2[t*100 + j], acc);
        logit[t] = acc;
    }
    __syncthreads();
    if (t == 0) {
        float m = -1e30f;
        #pragma unroll
        for (int e = 0; e < E; ++e) m = fmaxf(m, logit[e]);
        float s = 0.f; float ex[E];
        #pragma unroll
        for (int e = 0; e < E; ++e) { ex[e] = expf(logit[e] - m); s += ex[e]; }
        float inv = 1.0f / s;
        #pragma unroll
        for (int e = 0; e < E; ++e) g_gate[b*E + e] = ex[e] * inv;
    }
}

// ---------------- embedding + positional + LN1(blk0): warp per row ----------------
__global__ void k_embed_ln(const float* __restrict__ item_emb,
                           const float* __restrict__ pos_emb,
                           const int* __restrict__ log_seqs,
                           const float* __restrict__ g, const float* __restrict__ bb) {
    int warp = (blockIdx.x*blockDim.x + threadIdx.x) >> 5;
    int lane = threadIdx.x & 31;
    if (warp >= B*L) return;
    int l = warp % L;
    int it = log_seqs[warp];
    int pos = (it != 0) ? (l + 1) : 0;
    float x0 = 0.f, x1 = 0.f;
    if (lane < D)
        x0 = item_emb[it*D + lane] * 7.0710678118654755f + pos_emb[pos*D + lane];
    if (lane + 32 < D)
        x1 = item_emb[it*D + lane + 32] * 7.0710678118654755f + pos_emb[pos*D + lane + 32];
    if (lane < D)      g_seqs[warp*D + lane]      = x0;
    if (lane + 32 < D) g_seqs[warp*D + lane + 32] = x1;
    float s = x0 + x1;
    #pragma unroll
    for (int o = 16; o; o >>= 1) s += __shfl_xor_sync(~0u, s, o);
    float m = s * (1.0f / D);
    float d0 = (lane < D)      ? x0 - m : 0.f;
    float d1 = (lane + 32 < D) ? x1 - m : 0.f;
    float v = d0*d0 + d1*d1;
    #pragma unroll
    for (int o = 16; o; o >>= 1) v += __shfl_xor_sync(~0u, v, o);
    float inv = rsqrtf(v * (1.0f / D) + 1e-8f);
    if (lane < D)      g_Qn[warp*D + lane]      = fmaf(d0*inv, g[lane],      bb[lane]);
    if (lane + 32 < D) g_Qn[warp*D + lane + 32] = fmaf(d1*inv, g[lane + 32], bb[lane + 32]);
}

// ---------------- QKV v5: CTA per (b, rowhalf, experthalf); 2x10 tile; dense stores ----------------
// smem (ull units): XQ @0 [2525], XS @2525 [2525], W @5050 [3750], bias floats @8800
#define QKV_SMEM_BYTES (8800*8 + 152*4)

__global__ void __launch_bounds__(256) k_qkv(const float* __restrict__ in_w,
                                             const float* __restrict__ in_b, int blk) {
    extern __shared__ __align__(16) ull sm[];
    ull* XQ = sm;                  // [i*101 + row] (row local 0..99)
    ull* XS = sm + 2525;
    ull* W  = sm + 5050;           // [i*150 + f]
    float* sbias = (float*)(sm + 8800);
    int b = blockIdx.x;
    int l0 = blockIdx.y * 100;
    int e0 = blockIdx.z * 5;
    int tid = threadIdx.x;
    bool act = tid < 250;
    int fg = act ? tid / 50 : 0;       // 0..4 (feature group / head)
    int rg = act ? tid - fg*50 : 0;    // 0..49 -> local rows rg, rg+50

    // stage X transposed (once)
    {
        const ull* gq = (const ull*)g_Qn   + ((size_t)b*L + l0)*25;
        const ull* gs = (const ull*)g_seqs + ((size_t)b*L + l0)*25;
        for (int o = tid; o < 2500; o += 256) {
            int row = o / 25, i = o - row*25;
            XQ[i*101 + row] = gq[o];
            XS[i*101 + row] = gs[o];
        }
    }

    #pragma unroll 1
    for (int e = e0; e < e0 + 5; ++e) {
        __syncthreads();
        {
            const ull* Wg = (const ull*)(in_w + (size_t)(blk*E + e)*7500);
            for (int o = tid; o < 3750; o += 256) {
                int f = o / 25, i = o - f*25;
                W[i*150 + f] = Wg[o];
            }
            for (int o = tid; o < 150; o += 256) sbias[o] = in_b[(blk*E + e)*150 + o];
        }
        __syncthreads();

        #pragma unroll 1
        for (int pass = 0; pass < 3; ++pass) {
            const ull* X = (pass == 0) ? XQ : XS;
            int f0 = pass*50 + fg*10;
            ull acc[2][10];
            #pragma unroll
            for (int r = 0; r < 2; ++r)
                #pragma unroll
                for (int j = 0; j < 10; ++j) acc[r][j] = 0ull;
            #pragma unroll
            for (int i = 0; i < 25; ++i) {
                ull x0 = X[i*101 + rg];
                ull x1 = X[i*101 + rg + 50];
                const ull* wp = W + i*150 + f0;   // uniform across warp -> broadcast
                #pragma unroll
                for (int j2 = 0; j2 < 5; ++j2) {
                    ulonglong2 w2 = *(const ulonglong2*)(wp + 2*j2);
                    FMA2(acc[0][2*j2],   w2.x, x0, acc[0][2*j2]);
                    FMA2(acc[0][2*j2+1], w2.y, x0, acc[0][2*j2+1]);
                    FMA2(acc[1][2*j2],   w2.x, x1, acc[1][2*j2]);
                    FMA2(acc[1][2*j2+1], w2.y, x1, acc[1][2*j2+1]);
                }
            }
            if (act) {
                float* arr = (pass == 0) ? g_q : (pass == 1) ? g_k : g_v;
                ull* dst = (ull*)arr + ((size_t)(b*E + e)*H + fg)*1000;
                #pragma unroll
                for (int r = 0; r < 2; ++r) {
                    int row = l0 + rg + 50*r;
                    #pragma unroll
                    for (int j2 = 0; j2 < 5; ++j2) {
                        float v0 = hadd2(acc[r][2*j2])   + sbias[f0 + 2*j2];
                        float v1 = hadd2(acc[r][2*j2+1]) + sbias[f0 + 2*j2 + 1];
                        dst[j2*200 + row] = pack2(v0, v1);   // dense across lanes
                    }
                }
            }
        }
    }
}

// ---------------- attention: causal-balanced split + ex2 + predicate-free body ----------------
__global__ void __launch_bounds__(128) k_attn() {
    int id = blockIdx.x;            // (b*E+e)*H + h
    int h = id % H; int be = id / H;
    __shared__ __align__(16) ull ks[1000];   // row-major [j*5 + d2]
    __shared__ __align__(16) ull vs[1000];
    {
        const ull* kb = (const ull*)g_k + (size_t)(be*H + h)*1000;   // [d2*200 + l]
        const ull* vb = (const ull*)g_v + (size_t)(be*H + h)*1000;
        for (int o = threadIdx.x; o < 1000; o += 128) {
            int d2 = o / 200, l = o - d2*200;
            ks[l*5 + d2] = kb[o];
            vs[l*5 + d2] = vb[o];
        }
    }
    __syncthreads();
    int w = threadIdx.x >> 5, lane = threadIdx.x & 31;
    // causal-balanced split: minimizes sum of per-warp jmax
    const int wbase = (w == 0) ? 0 : (w == 1) ? 8 : (w == 2) ? 72 : 136;
    const int wend  = (w == 0) ? 8 : (w == 1) ? 72 : (w == 2) ? 136 : 200;
    int nl = (wend - wbase) >> 1;           // active lanes: 4 or 32
    bool valid = lane < nl;
    int li = valid ? lane : (nl - 1);
    int r0 = wbase + 2*li, r1 = r0 + 1;
    // scale = log2(e)/sqrt(10): use ex2 so no per-j multiply
    const float scale = 0.31622776601683794f * 1.4426950408889634f;
    ull q0[5], q1[5];
    {
        const ull* qb = (const ull*)g_q + (size_t)(be*H + h)*1000;
        ull sc2 = pack2(scale, scale);
        #pragma unroll
        for (int d = 0; d < 5; ++d) {
            ulonglong2 qq = *(const ulonglong2*)(qb + d*200 + r0);   // rows r0, r1
            MUL2(q0[d], qq.x, sc2);
            MUL2(q1[d], qq.y, sc2);
        }
    }
    float ps0 = 0.f, ps1 = 0.f;
    ull a0[5] = {0,0,0,0,0}, a1[5] = {0,0,0,0,0};
    // body: j <= wbase <= r0 for every lane -> no causal predicate
    #pragma unroll 2
    for (int j = 0; j <= wbase; ++j) {
        const ull* kj = ks + j*5;
        const ull* vj = vs + j*5;
        ull s0 = 0ull, s1 = 0ull;
        #pragma unroll
        for (int d = 0; d < 5; ++d) {
            ull kd = kj[d];
            FMA2(s0, q0[d], kd, s0);
            FMA2(s1, q1[d], kd, s1);
        }
        float p0 = ex2f(hadd2(s0));
        float p1 = ex2f(hadd2(s1));
        ps0 += p0; ps1 += p1;
        ull pp0 = pack2(p0, p0), pp1 = pack2(p1, p1);
        #pragma unroll
        for (int d = 0; d < 5; ++d) {
            ull vd = vj[d];
            FMA2(a0[d], pp0, vd, a0[d]);
            FMA2(a1[d], pp1, vd, a1[d]);
        }
    }
    // tail: causal predicates needed
    #pragma unroll 2
    for (int j = wbase + 1; j < wend; ++j) {
        const ull* kj = ks + j*5;
        const ull* vj = vs + j*5;
        ull s0 = 0ull, s1 = 0ull;
        #pragma unroll
        for (int d = 0; d < 5; ++d) {
            ull kd = kj[d];
            FMA2(s0, q0[d], kd, s0);
            FMA2(s1, q1[d], kd, s1);
        }
        float p0 = (j <= r0) ? ex2f(hadd2(s0)) : 0.f;
        float p1 = (j <= r1) ? ex2f(hadd2(s1)) : 0.f;
        ps0 += p0; ps1 += p1;
        ull pp0 = pack2(p0, p0), pp1 = pack2(p1, p1);
        #pragma unroll
        for (int d = 0; d < 5; ++d) {
            ull vd = vj[d];
            FMA2(a0[d], pp0, vd, a0[d]);
            FMA2(a1[d], pp1, vd, a1[d]);
        }
    }
    if (valid) {
        int b = be / E, e = be - b*E;
        float gt = g_gate[b*E + e];
        float i0 = gt / ps0, i1 = gt / ps1;
        ull* c0 = (ull*)g_ctx + ((size_t)be*L + r0)*25 + h*5;
        ull* c1 = (ull*)g_ctx + ((size_t)be*L + r1)*25 + h*5;
        #pragma unroll
        for (int d = 0; d < 5; ++d) {
            float lo, hi;
            unpk2(a0[d], lo, hi); c0[d] = pack2(lo*i0, hi*i0);
            unpk2(a1[d], lo, hi); c1[d] = pack2(lo*i1, hi*i1);
        }
    }
}

// ---------------- out-proj + bias-mix + residual + LN2 fused: CTA per (b, half) ----------------
__global__ void __launch_bounds__(256) k_combine(const float* __restrict__ out_w,
                                                 const float* __restrict__ out_b,
                                                 const float* __restrict__ ln_g,
                                                 const float* __restrict__ ln_b, int blk) {
    __shared__ __align__(16) ull CT[2525];   // transposed ctx [i*101 + row]; reused as SOUT
    __shared__ __align__(16) ull WT[1250];   // [i*50 + f] W[f][2i..2i+1]
    int b = blockIdx.x;
    int l0 = blockIdx.y * 100;
    int tid = threadIdx.x;
    bool act = tid < 250;
    int fg = tid / 50;           // 0..4
    int rg = tid - fg*50;        // rows rg, rg+50 (local)
    ull acc[2][10];
    #pragma unroll
    for (int r = 0; r < 2; ++r)
        #pragma unroll
        for (int j = 0; j < 10; ++j) acc[r][j] = 0ull;
    float bm[10];
    #pragma unroll
    for (int j = 0; j < 10; ++j) bm[j] = 0.f;

    for (int e = 0; e < E; ++e) {
        __syncthreads();
        {
            const ull* Wg = (const ull*)(out_w + (size_t)(blk*E + e)*2500);
            for (int o = tid; o < 1250; o += 256) {
                int f = o / 25, i = o - f*25;
                WT[i*50 + f] = Wg[o];
            }
            const ull* cg = (const ull*)g_ctx + ((size_t)(b*E + e)*L + l0)*25;
            for (int o = tid; o < 2500; o += 256) {
                int row = o / 25, i = o - row*25;
                CT[i*101 + row] = cg[o];
            }
        }
        float ge = g_gate[b*E + e];
        if (act) {
            #pragma unroll
            for (int j = 0; j < 10; ++j)
                bm[j] = fmaf(ge, out_b[(blk*E + e)*D + fg*10 + j], bm[j]);
        }
        __syncthreads();
        if (act) {
            #pragma unroll 5
            for (int i = 0; i < 25; ++i) {
                ull x0 = CT[i*101 + rg];
                ull x1 = CT[i*101 + rg + 50];
                const ull* wp = WT + i*50 + fg*10;
                #pragma unroll
                for (int j2 = 0; j2 < 5; ++j2) {
                    ulonglong2 w2 = *(const ulonglong2*)(wp + 2*j2);
                    FMA2(acc[0][2*j2],   w2.x, x0, acc[0][2*j2]);
                    FMA2(acc[0][2*j2+1], w2.y, x0, acc[0][2*j2+1]);
                    FMA2(acc[1][2*j2],   w2.x, x1, acc[1][2*j2]);
                    FMA2(acc[1][2*j2+1], w2.y, x1, acc[1][2*j2+1]);
                }
            }
        }
    }
    __syncthreads();
    if (act) {
        #pragma unroll
        for (int r = 0; r < 2; ++r) {
            int row = rg + 50*r;
            #pragma unroll
            for (int j2 = 0; j2 < 5; ++j2) {
                float v0 = hadd2(acc[r][2*j2])   + bm[2*j2];
                float v1 = hadd2(acc[r][2*j2+1]) + bm[2*j2+1];
                CT[row*25 + fg*5 + j2] = pack2(v0, v1);   // SOUT (gated sum + bias-mix)
            }
        }
    }
    __syncthreads();
    // fused: tmp = SOUT + Qn (residual); g_seqs = LN2(tmp)
    {
        int wid = tid >> 5, lane = tid & 31;
        float ga = 0.f, gb = 0.f, ba = 0.f, bbv = 0.f;
        if (lane < 25) {
            ga = ln_g[2*lane]; gb = ln_g[2*lane + 1];
            ba = ln_b[2*lane]; bbv = ln_b[2*lane + 1];
        }
        for (int r = wid; r < 100; r += 8) {
            size_t gro = ((size_t)b*L + l0 + r)*25 + lane;
            float a = 0.f, c = 0.f;
            if (lane < 25) {
                float s0, s1, q0, q1;
                unpk2(CT[r*25 + lane], s0, s1);
                unpk2(((const ull*)g_Qn)[gro], q0, q1);
                a = s0 + q0; c = s1 + q1;
            }
            float s = a + c;
            #pragma unroll
            for (int o = 16; o; o >>= 1) s += __shfl_xor_sync(~0u, s, o);
            float m = s * (1.0f / D);
            float da = (lane < 25) ? a - m : 0.f;
            float dc = (lane < 25) ? c - m : 0.f;
            float v = da*da + dc*dc;
            #pragma unroll
            for (int o = 16; o; o >>= 1) v += __shfl_xor_sync(~0u, v, o);
            float inv = rsqrtf(v * (1.0f / D) + 1e-8f);
            if (lane < 25) {
                float y0 = fmaf(da*inv, ga, ba);
                float y1 = fmaf(dc*inv, gb, bbv);
                ((ull*)g_seqs)[gro] = pack2(y0, y1);
            }
        }
    }
}

// ---------------- FFN + residual + LN1(next blk) fused: CTA per (b, half) ----------------
#define FFN_SMEM_BYTES (7550*8 + 104*4)

__global__ void __launch_bounds__(256) k_ffn(const float* __restrict__ f1_w, const float* __restrict__ f1_b,
                                             const float* __restrict__ f2_w, const float* __restrict__ f2_b,
                                             const float* __restrict__ ln_g, const float* __restrict__ ln_b,
                                             int blk, int has_next) {
    extern __shared__ __align__(16) ull sf[];
    ull* XT  = sf;            // [i*101 + row]; later reused as SOUT (row*25 + i)
    ull* HT  = sf + 2525;
    ull* W1T = sf + 5050;
    ull* W2T = sf + 6300;
    float* b1s = (float*)(sf + 7550);
    float* b2s = b1s + 50;
    int b = blockIdx.x;
    int l0 = blockIdx.y * 100;
    int tid = threadIdx.x;
    bool act = tid < 250;
    int fg = act ? tid / 50 : 0;
    int rg = act ? tid - fg*50 : 0;

    {
        const ull* gs = (const ull*)g_seqs + ((size_t)b*L + l0)*25;
        for (int o = tid; o < 2500; o += 256) {
            int row = o / 25, i = o - row*25;
            XT[i*101 + row] = gs[o];
        }
        const ull* W1g = (const ull*)(f1_w + (size_t)blk*2500);
        const ull* W2g = (const ull*)(f2_w + (size_t)blk*2500);
        for (int o = tid; o < 1250; o += 256) {
            int f = o / 25, i = o - f*25;
            W1T[i*50 + f] = W1g[o];
            W2T[i*50 + f] = W2g[o];
        }
        if (tid < 50) { b1s[tid] = f1_b[blk*D + tid]; b2s[tid] = f2_b[blk*D + tid]; }
    }
    __syncthreads();

    int f0 = fg*10;
    {
        ull acc[2][10];
        #pragma unroll
        for (int r = 0; r < 2; ++r)
            #pragma unroll
            for (int j = 0; j < 10; ++j) acc[r][j] = 0ull;
        #pragma unroll 5
        for (int i = 0; i < 25; ++i) {
            ull x0 = XT[i*101 + rg];
            ull x1 = XT[i*101 + rg + 50];
            const ull* wp = W1T + i*50 + f0;
            #pragma unroll
            for (int j2 = 0; j2 < 5; ++j2) {
                ulonglong2 w2 = *(const ulonglong2*)(wp + 2*j2);
                FMA2(acc[0][2*j2],   w2.x, x0, acc[0][2*j2]);
                FMA2(acc[0][2*j2+1], w2.y, x0, acc[0][2*j2+1]);
                FMA2(acc[1][2*j2],   w2.x, x1, acc[1][2*j2]);
                FMA2(acc[1][2*j2+1], w2.y, x1, acc[1][2*j2+1]);
            }
        }
        if (act) {
            #pragma unroll
            for (int r = 0; r < 2; ++r) {
                #pragma unroll
                for (int j2 = 0; j2 < 5; ++j2) {
                    float h0 = fmaxf(hadd2(acc[r][2*j2])   + b1s[f0 + 2*j2],     0.f);
                    float h1 = fmaxf(hadd2(acc[r][2*j2+1]) + b1s[f0 + 2*j2 + 1], 0.f);
                    HT[(fg*5 + j2)*101 + rg + 50*r] = pack2(h0, h1);
                }
            }
        }
    }
    __syncthreads();
    {
        ull acc[2][10];
        #pragma unroll
        for (int r = 0; r < 2; ++r)
            #pragma unroll
            for (int j = 0; j < 10; ++j) acc[r][j] = 0ull;
        #pragma unroll 5
        for (int i = 0; i < 25; ++i) {
            ull h0 = HT[i*101 + rg];
            ull h1 = HT[i*101 + rg + 50];
            const ull* wp = W2T + i*50 + f0;
            #pragma unroll
            for (int j2 = 0; j2 < 5; ++j2) {
                ulonglong2 w2 = *(const ulonglong2*)(wp + 2*j2);
                FMA2(acc[0][2*j2],   w2.x, h0, acc[0][2*j2]);
                FMA2(acc[0][2*j2+1], w2.y, h0, acc[0][2*j2+1]);
                FMA2(acc[1][2*j2],   w2.x, h1, acc[1][2*j2]);
                FMA2(acc[1][2*j2+1], w2.y, h1, acc[1][2*j2+1]);
            }
        }
        if (act) {
            #pragma unroll
            for (int r = 0; r < 2; ++r) {
                int row = rg + 50*r;
                #pragma unroll
                for (int j2 = 0; j2 < 5; ++j2) {
                    float o0 = hadd2(acc[r][2*j2])   + b2s[f0 + 2*j2];
                    float o1 = hadd2(acc[r][2*j2+1]) + b2s[f0 + 2*j2 + 1];
                    XT[row*25 + fg*5 + j2] = pack2(o0, o1);   // SOUT (ffn output, pre-residual)
                }
            }
        }
    }
    __syncthreads();
    // fused: x = SOUT + seqs (residual) -> g_seqs; g_Qn = LN1_next(x) when has_next
    {
        int wid = tid >> 5, lane = tid & 31;
        float ga = 0.f, gb = 0.f, ba = 0.f, bbv = 0.f;
        if (has_next && lane < 25) {
            ga = ln_g[2*lane]; gb = ln_g[2*lane + 1];
            ba = ln_b[2*lane]; bbv = ln_b[2*lane + 1];
        }
        for (int r = wid; r < 100; r += 8) {
            size_t gro = ((size_t)b*L + l0 + r)*25 + lane;
            float a = 0.f, c = 0.f;
            if (lane < 25) {
                float s0, s1, q0, q1;
                unpk2(XT[r*25 + lane], s0, s1);
                unpk2(((const ull*)g_seqs)[gro], q0, q1);
                a = s0 + q0; c = s1 + q1;
                ((ull*)g_seqs)[gro] = pack2(a, c);
            }
            if (has_next) {
                float s = a + c;
                #pragma unroll
                for (int o = 16; o; o >>= 1) s += __shfl_xor_sync(~0u, s, o);
                float m = s * (1.0f / D);
                float da = (lane < 25) ? a - m : 0.f;
                float dc = (lane < 25) ? c - m : 0.f;
                float v = da*da + dc*dc;
                #pragma unroll
                for (int o = 16; o; o >>= 1) v += __shfl_xor_sync(~0u, v, o);
                float inv = rsqrtf(v * (1.0f / D) + 1e-8f);
                if (lane < 25) {
                    float y0 = fmaf(da*inv, ga, ba);
                    float y1 = fmaf(dc*inv, gb, bbv);
                    ((ull*)g_Qn)[gro] = pack2(y0, y1);
                }
            }
        }
    }
}

// ---------------- final LN + pos/neg logits ----------------
__global__ void k_final(const float* __restrict__ lnf_g, const float* __restrict__ lnf_b,
                        const float* __restrict__ item_emb,
                        const int* __restrict__ pos_seqs, const int* __restrict__ neg_seqs,
                        float* __restrict__ out) {
    int warp = (blockIdx.x*blockDim.x + threadIdx.x) >> 5;
    int lane = threadIdx.x & 31;
    if (warp >= B*L) return;
    const float* x = g_seqs + warp*D;
    float x0 = (lane < D)      ? x[lane]      : 0.f;
    float x1 = (lane + 32 < D) ? x[lane + 32] : 0.f;
    float s = x0 + x1;
    #pragma unroll
    for (int o = 16; o; o >>= 1) s += __shfl_xor_sync(~0u, s, o);
    float m = s * (1.0f / D);
    float d0 = (lane < D)      ? x0 - m : 0.f;
    float d1 = (lane + 32 < D) ? x1 - m : 0.f;
    float v = d0*d0 + d1*d1;
    #pragma unroll
    for (int o = 16; o; o >>= 1) v += __shfl_xor_sync(~0u, v, o);
    float inv = rsqrtf(v * (1.0f / D) + 1e-8f);
    float f0 = (lane < D)      ? fmaf(d0*inv, lnf_g[lane],      lnf_b[lane])      : 0.f;
    float f1 = (lane + 32 < D) ? fmaf(d1*inv, lnf_g[lane + 32], lnf_b[lane + 32]) : 0.f;
    int ip = pos_seqs[warp], in_ = neg_seqs[warp];
    const float* pe = item_emb + (size_t)ip*D;
    const float* ne = item_emb + (size_t)in_*D;
    float dp = 0.f, dn = 0.f;
    if (lane < D)      { dp = f0*pe[lane];                 dn = f0*ne[lane]; }
    if (lane + 32 < D) { dp = fmaf(f1, pe[lane + 32], dp); dn = fmaf(f1, ne[lane + 32], dn); }
    #pragma unroll
    for (int o = 16; o; o >>= 1) {
        dp += __shfl_xor_sync(~0u, dp, o);
        dn += __shfl_xor_sync(~0u, dn, o);
    }
    if (lane == 0) { out[warp] = dp; out[B*L + warp] = dn; }
}

// ---------------- launch ----------------
extern "C" void kernel_launch(void* const* d_in, const int* in_sizes, int n_in,
                              void* d_out, int out_size) {
    const float* item_emb = (const float*)d_in[0];
    const float* pos_emb  = (const float*)d_in[1];
    const float* rW1      = (const float*)d_in[2];
    const float* rb1      = (const float*)d_in[3];
    const float* rW2      = (const float*)d_in[4];
    const float* rb2      = (const float*)d_in[5];
    const float* ln1_g    = (const float*)d_in[6];
    const float* ln1_b    = (const float*)d_in[7];
    const float* in_w     = (const float*)d_in[8];
    const float* in_b     = (const float*)d_in[9];
    const float* out_w    = (const float*)d_in[10];
    const float* out_b    = (const float*)d_in[11];
    const float* ln2_g    = (const float*)d_in[12];
    const float* ln2_b    = (const float*)d_in[13];
    const float* f1_w     = (const float*)d_in[14];
    const float* f1_b     = (const float*)d_in[15];
    const float* f2_w     = (const float*)d_in[16];
    const float* f2_b     = (const float*)d_in[17];
    const float* lnf_g    = (const float*)d_in[18];
    const float* lnf_b    = (const float*)d_in[19];
    const int*   log_seqs = (const int*)d_in[21];
    const int*   pos_seqs = (const int*)d_in[22];
    const int*   neg_seqs = (const int*)d_in[23];
    float* out = (float*)d_out;

    cudaFuncSetAttribute(k_qkv, cudaFuncAttributeMaxDynamicSharedMemorySize, QKV_SMEM_BYTES);
    cudaFuncSetAttribute(k_ffn, cudaFuncAttributeMaxDynamicSharedMemorySize, FFN_SMEM_BYTES);

    k_gate<<<B, 128>>>(item_emb, rW1, rb1, rW2, rb2, log_seqs);
    k_embed_ln<<<(B*L + 7)/8, 256>>>(item_emb, pos_emb, log_seqs, ln1_g, ln1_b);

    for (int blk = 0; blk < NB; ++blk) {
        k_qkv<<<dim3(B, 2, 2), 256, QKV_SMEM_BYTES>>>(in_w, in_b, blk);
        k_attn<<<B*E*H, 128>>>();
        k_combine<<<dim3(B, 2), 256>>>(out_w, out_b, ln2_g + blk*D, ln2_b + blk*D, blk);
        int has_next = (blk + 1 < NB) ? 1 : 0;
        k_ffn<<<dim3(B, 2), 256, FFN_SMEM_BYTES>>>(f1_w, f1_b, f2_w, f2_b,
                                                   ln1_g + (blk+1 < NB ? (blk+1)*D : 0),
                                                   ln1_b + (blk+1 < NB ? (blk+1)*D : 0),
                                                   blk, has_next);
    }

    k_final<<<(B*L + 7)/8, 256>>>(lnf_g, lnf_b, item_emb, pos_seqs, neg_seqs, out);
}